// round 2
// baseline (speedup 1.0000x reference)
#include <cuda_runtime.h>
#include <math.h>

// Problem constants (PaGNN): N=100000 nodes, E=1600000 edges, D=128, H=128, C=40
#define NN 100000
#define DF 128
#define NC 40

// Scratch (device globals; no runtime allocation allowed)
__device__ float g_agg [NN * DF];   // masked-sum aggregation
__device__ float g_degf[NN * DF];   // per-feature observed-neighbor counts
__device__ float g_h1  [NN * DF];   // relu(conv1)
__device__ float g_xw  [NN * NC];   // h1 @ W2 (no bias)
__device__ float g_deg2[NN];        // GCN in-degree (edges only; +1 self added later)
__device__ float g_dinv[NN];        // rsqrt(deg2+1)

__device__ __forceinline__ void red_add_v4(float* addr, float a, float b, float c, float d) {
    asm volatile("red.global.add.v4.f32 [%0], {%1, %2, %3, %4};"
                 :: "l"(addr), "f"(a), "f"(b), "f"(c), "f"(d)
                 : "memory");
}

// ---------------------------------------------------------------------------
// 0) zero scratch + output
// ---------------------------------------------------------------------------
__global__ void zero_kernel(float4* __restrict__ out4, int n_out4) {
    int i = blockIdx.x * blockDim.x + threadIdx.x;
    float4 z = make_float4(0.f, 0.f, 0.f, 0.f);
    if (i < NN * DF / 4) {
        reinterpret_cast<float4*>(g_agg)[i]  = z;
        reinterpret_cast<float4*>(g_degf)[i] = z;
    }
    if (i < n_out4) out4[i] = z;
    if (i < NN / 4) reinterpret_cast<float4*>(g_deg2)[i] = z;
}

// ---------------------------------------------------------------------------
// 1) pass-1 edge scatter: agg[row] += x[col]*mask[col]; degf[row] += mask[col]
//    one warp per edge, 4 feats per lane via float4 + vector red.
//    mask is treated as 32-bit words (works for int32 0/1 AND float32 0.0/1.0:
//    nonzero bit pattern <=> true).
// ---------------------------------------------------------------------------
__global__ void scatter1_kernel(const float* __restrict__ x,
                                const unsigned int* __restrict__ mask,
                                const int* __restrict__ row,
                                const int* __restrict__ col,
                                int E) {
    int warp = (blockIdx.x * blockDim.x + threadIdx.x) >> 5;
    int lane = threadIdx.x & 31;
    if (warp >= E) return;
    int r = row[warp];
    int c = col[warp];

    float4 xv = reinterpret_cast<const float4*>(x + (size_t)c * DF)[lane];
    uint4  mv = reinterpret_cast<const uint4*>(mask + (size_t)c * DF)[lane];
    float m0 = mv.x ? 1.0f : 0.0f;
    float m1 = mv.y ? 1.0f : 0.0f;
    float m2 = mv.z ? 1.0f : 0.0f;
    float m3 = mv.w ? 1.0f : 0.0f;

    float* aggp = g_agg  + (size_t)r * DF + lane * 4;
    float* degp = g_degf + (size_t)r * DF + lane * 4;
    red_add_v4(aggp, xv.x * m0, xv.y * m1, xv.z * m2, xv.w * m3);
    red_add_v4(degp, m0, m1, m2, m3);
    if (lane == 0) atomicAdd(&g_deg2[r], 1.0f);
}

// ---------------------------------------------------------------------------
// 2) h1 = relu((agg / max(degf,1)) @ W1 + b1)
//    128 threads/block, W1 (64KB) in dynamic shared, 32 nodes per block
// ---------------------------------------------------------------------------
__global__ void gemm1_kernel(const float* __restrict__ W1,
                             const float* __restrict__ b1,
                             int n) {
    extern __shared__ float sh[];
    float* shW = sh;           // 128*128
    float* shH = sh + 128*128; // 128
    int tid = threadIdx.x;

    for (int i = tid; i < 128 * 128; i += 128) shW[i] = W1[i];
    float bj = b1[tid];
    __syncthreads();

    int base = blockIdx.x * 32;
    for (int s = 0; s < 32; s++) {
        int node = base + s;
        if (node >= n) break;
        float a = g_agg [(size_t)node * 128 + tid];
        float d = g_degf[(size_t)node * 128 + tid];
        shH[tid] = a / fmaxf(d, 1.0f);
        __syncthreads();
        float acc = bj;
        #pragma unroll
        for (int k = 0; k < 128; k++)
            acc = fmaf(shH[k], shW[k * 128 + tid], acc);
        g_h1[(size_t)node * 128 + tid] = fmaxf(acc, 0.0f);
        __syncthreads();
    }
}

// ---------------------------------------------------------------------------
// 3) xw = h1 @ W2    (NO bias here — bias is added once in the epilogue,
//    because the reference adds b2 AFTER the GCN segment sum)
// ---------------------------------------------------------------------------
__global__ void gemm2_kernel(const float* __restrict__ W2,
                             int n) {
    __shared__ float shW[128 * 40];
    __shared__ float shH[16 * 128];
    int tid = threadIdx.x;

    for (int i = tid; i < 128 * 40; i += 128) shW[i] = W2[i];
    __syncthreads();

    int base = blockIdx.x * 16;
    for (int i = tid; i < 16 * 128; i += 128) {
        int node = base + (i >> 7);
        shH[i] = (node < n) ? g_h1[(size_t)base * 128 + i] : 0.0f;
    }
    __syncthreads();

    for (int o = tid; o < 16 * 40; o += 128) {
        int s = o / 40;
        int j = o - s * 40;
        int node = base + s;
        if (node < n) {
            float acc = 0.0f;
            #pragma unroll
            for (int k = 0; k < 128; k++)
                acc = fmaf(shH[s * 128 + k], shW[k * 40 + j], acc);
            g_xw[(size_t)node * 40 + j] = acc;
        }
    }
}

// ---------------------------------------------------------------------------
// 4) dinv = rsqrt(deg_edges + 1)   (self loop; always >= 1 so no clip branch)
// ---------------------------------------------------------------------------
__global__ void dinv_kernel(int n) {
    int i = blockIdx.x * blockDim.x + threadIdx.x;
    if (i < n) g_dinv[i] = rsqrtf(g_deg2[i] + 1.0f);
}

// ---------------------------------------------------------------------------
// 5) pass-2 edge scatter: out[row] += dinv[row]*dinv[col] * xw[col]
//    40 floats = 10 float4 per edge; thread t handles (edge t/10, quarter t%10)
// ---------------------------------------------------------------------------
__global__ void scatter2_kernel(const int* __restrict__ row,
                                const int* __restrict__ col,
                                float* __restrict__ out,
                                int E) {
    int t = blockIdx.x * blockDim.x + threadIdx.x;
    int e = t / 10;
    int p = t - e * 10;
    if (e >= E) return;
    int r = row[e];
    int c = col[e];
    float coef = g_dinv[r] * g_dinv[c];
    float4 v = reinterpret_cast<const float4*>(g_xw)[(size_t)c * 10 + p];
    float* dst = reinterpret_cast<float*>(
        reinterpret_cast<float4*>(out) + (size_t)r * 10 + p);
    red_add_v4(dst, v.x * coef, v.y * coef, v.z * coef, v.w * coef);
}

// ---------------------------------------------------------------------------
// 6) epilogue: add self-loop + bias (once), then row-wise log_softmax
//    (one warp per node)
// ---------------------------------------------------------------------------
__global__ void epilogue_kernel(const float* __restrict__ b2,
                                float* __restrict__ out,
                                int n) {
    int warp = (blockIdx.x * blockDim.x + threadIdx.x) >> 5;
    int lane = threadIdx.x & 31;
    if (warp >= n) return;
    float di = g_dinv[warp];
    float d2 = di * di;
    size_t base = (size_t)warp * NC;

    float v0 = out[base + lane] + d2 * g_xw[base + lane] + b2[lane];
    float v1 = -INFINITY;
    if (lane < NC - 32)
        v1 = out[base + 32 + lane] + d2 * g_xw[base + 32 + lane] + b2[32 + lane];

    float m = fmaxf(v0, v1);
    #pragma unroll
    for (int o = 16; o > 0; o >>= 1)
        m = fmaxf(m, __shfl_xor_sync(0xffffffffu, m, o));

    float s = expf(v0 - m) + ((lane < NC - 32) ? expf(v1 - m) : 0.0f);
    #pragma unroll
    for (int o = 16; o > 0; o >>= 1)
        s += __shfl_xor_sync(0xffffffffu, s, o);

    float lse = logf(s);
    out[base + lane] = v0 - m - lse;
    if (lane < NC - 32) out[base + 32 + lane] = v1 - m - lse;
}

// ---------------------------------------------------------------------------
extern "C" void kernel_launch(void* const* d_in, const int* in_sizes, int n_in,
                              void* d_out, int out_size) {
    const float*        x    = (const float*)d_in[0];
    const unsigned int* mask = (const unsigned int*)d_in[1];
    const int*          eidx = (const int*)d_in[2];
    const float*        W1   = (const float*)d_in[3];
    const float*        b1   = (const float*)d_in[4];
    const float*        W2   = (const float*)d_in[5];
    const float*        b2   = (const float*)d_in[6];
    float* out = (float*)d_out;

    const int N = in_sizes[0] / DF;      // 100000
    const int E = in_sizes[2] / 2;       // 1600000
    const int* row = eidx;
    const int* col = eidx + E;

    // 0) zero scratch + output
    {
        int n_out4 = out_size / 4;
        int total = NN * DF / 4;
        zero_kernel<<<(total + 255) / 256, 256>>>((float4*)out, n_out4);
    }

    // 1) pass-1 scatter: one warp per edge, 8 warps per block
    {
        int blocks = (E + 7) / 8;
        scatter1_kernel<<<blocks, 256>>>(x, mask, row, col, E);
    }

    // 2) conv1 GEMM + relu
    {
        int smem = (128 * 128 + 128) * (int)sizeof(float);
        cudaFuncSetAttribute(gemm1_kernel, cudaFuncAttributeMaxDynamicSharedMemorySize, smem);
        int blocks = (N + 31) / 32;
        gemm1_kernel<<<blocks, 128, smem>>>(W1, b1, N);
    }

    // 3) conv2 dense part (no bias)
    {
        int blocks = (N + 15) / 16;
        gemm2_kernel<<<blocks, 128>>>(W2, N);
    }

    // 4) degree normalization
    dinv_kernel<<<(N + 255) / 256, 256>>>(N);

    // 5) pass-2 scatter into out
    {
        long long threads = (long long)E * 10;
        int blocks = (int)((threads + 255) / 256);
        scatter2_kernel<<<blocks, 256>>>(row, col, out, E);
    }

    // 6) self-loop + bias + log_softmax
    {
        int blocks = (N + 7) / 8;  // 8 warps per block
        epilogue_kernel<<<blocks, 256>>>(b2, out, N);
    }
}

// round 3
// speedup vs baseline: 1.3873x; 1.3873x over previous
#include <cuda_runtime.h>
#include <math.h>

// PaGNN: N=100000 nodes, E=1600000 edges, D=128, H=128, C=40
#define NN 100000
#define DF 128
#define NC 40

// ---- scratch (device globals; no runtime allocation allowed) ---------------
__device__ float g_xm   [NN * DF];     // x * mask (pre-masked features)
__device__ uint4 g_mbits[NN];          // 128-bit mask per node (ballot layout)
__device__ float g_hin  [NN * DF];     // normalized aggregation (conv1 input)
__device__ float g_h1   [NN * DF];     // relu(conv1)
__device__ float g_xw   [NN * NC];     // h1 @ W2 (no bias)
__device__ int   g_rowcnt[NN];         // in-degree histogram
__device__ int   g_rowptr[NN + 1];     // CSR row pointers
__device__ int   g_wpos [NN];          // running write positions for bucket fill
__device__ int   g_scol [2000000];     // CSR column indices (cap > E)
__device__ float g_dinv [NN];          // rsqrt(deg+1)

// ---------------------------------------------------------------------------
// 0) zero the histogram
// ---------------------------------------------------------------------------
__global__ void zero_kernel() {
    int i = blockIdx.x * blockDim.x + threadIdx.x;
    if (i < NN) g_rowcnt[i] = 0;
}

// ---------------------------------------------------------------------------
// 1) prep: xm = x*mask, 128-bit mask bitmap per node (ballot layout:
//    word i bit `lane` = mask[node][4*lane + i]); one warp per node
// ---------------------------------------------------------------------------
__global__ void prep_kernel(const float* __restrict__ x,
                            const unsigned int* __restrict__ mask,
                            int n) {
    int node = (blockIdx.x * blockDim.x + threadIdx.x) >> 5;
    int lane = threadIdx.x & 31;
    if (node >= n) return;

    float4 xv = reinterpret_cast<const float4*>(x)[(size_t)node * 32 + lane];
    uint4  mv = reinterpret_cast<const uint4*>(mask)[(size_t)node * 32 + lane];

    float4 xm;
    xm.x = mv.x ? xv.x : 0.0f;
    xm.y = mv.y ? xv.y : 0.0f;
    xm.z = mv.z ? xv.z : 0.0f;
    xm.w = mv.w ? xv.w : 0.0f;
    reinterpret_cast<float4*>(g_xm)[(size_t)node * 32 + lane] = xm;

    unsigned b0 = __ballot_sync(0xffffffffu, mv.x != 0u);
    unsigned b1 = __ballot_sync(0xffffffffu, mv.y != 0u);
    unsigned b2 = __ballot_sync(0xffffffffu, mv.z != 0u);
    unsigned b3 = __ballot_sync(0xffffffffu, mv.w != 0u);
    if (lane == 0) g_mbits[node] = make_uint4(b0, b1, b2, b3);
}

// ---------------------------------------------------------------------------
// 2) histogram of destination rows
// ---------------------------------------------------------------------------
__global__ void hist_kernel(const int* __restrict__ row, int E) {
    int e = blockIdx.x * blockDim.x + threadIdx.x;
    if (e < E) atomicAdd(&g_rowcnt[row[e]], 1);
}

// ---------------------------------------------------------------------------
// 3) single-block exclusive scan (1024 threads x ~98 elems), also emits
//    dinv = rsqrt(cnt+1) and initializes write positions
// ---------------------------------------------------------------------------
__global__ void scan_kernel() {
    __shared__ int ssum[1024];
    int tid = threadIdx.x;
    const int CH = (NN + 1023) / 1024;   // 98
    int s0 = tid * CH;
    int s1 = min(s0 + CH, NN);

    int sum = 0;
    for (int i = s0; i < s1; i++) sum += g_rowcnt[i];
    ssum[tid] = sum;
    __syncthreads();

    // Hillis-Steele inclusive scan
    for (int off = 1; off < 1024; off <<= 1) {
        int v = (tid >= off) ? ssum[tid - off] : 0;
        __syncthreads();
        ssum[tid] += v;
        __syncthreads();
    }

    int prefix = (tid == 0) ? 0 : ssum[tid - 1];
    for (int i = s0; i < s1; i++) {
        int c = g_rowcnt[i];
        g_rowptr[i] = prefix;
        g_wpos[i]   = prefix;
        g_dinv[i]   = rsqrtf((float)c + 1.0f);
        prefix += c;
    }
    if (tid == 1023) g_rowptr[NN] = prefix;
}

// ---------------------------------------------------------------------------
// 4) bucket-fill CSR columns
// ---------------------------------------------------------------------------
__global__ void edges_kernel(const int* __restrict__ row,
                             const int* __restrict__ col, int E) {
    int e = blockIdx.x * blockDim.x + threadIdx.x;
    if (e >= E) return;
    int p = atomicAdd(&g_wpos[row[e]], 1);
    g_scol[p] = col[e];
}

// ---------------------------------------------------------------------------
// 5) pass-1 aggregation (gather): one warp per node, 4 feats/lane.
//    hin = (sum_{c in N(r)} xm[c]) / max(count_per_feat, 1)
// ---------------------------------------------------------------------------
__global__ void agg1_kernel(int n) {
    int node = (blockIdx.x * blockDim.x + threadIdx.x) >> 5;
    int lane = threadIdx.x & 31;
    if (node >= n) return;

    int s = g_rowptr[node];
    int e = g_rowptr[node + 1];

    float ax = 0.f, ay = 0.f, az = 0.f, aw = 0.f;
    int   cx = 0,   cy = 0,   cz = 0,   cw = 0;

    for (int j = s; j < e; j++) {
        int c = g_scol[j];
        float4 v  = reinterpret_cast<const float4*>(g_xm)[(size_t)c * 32 + lane];
        uint4  bw = g_mbits[c];
        ax += v.x; ay += v.y; az += v.z; aw += v.w;
        cx += (bw.x >> lane) & 1u;
        cy += (bw.y >> lane) & 1u;
        cz += (bw.z >> lane) & 1u;
        cw += (bw.w >> lane) & 1u;
    }

    float4 h;
    h.x = ax / fmaxf((float)cx, 1.0f);
    h.y = ay / fmaxf((float)cy, 1.0f);
    h.z = az / fmaxf((float)cz, 1.0f);
    h.w = aw / fmaxf((float)cw, 1.0f);
    reinterpret_cast<float4*>(g_hin)[(size_t)node * 32 + lane] = h;
}

// ---------------------------------------------------------------------------
// 6) h1 = relu(hin @ W1 + b1), register-tiled 4 nodes/thread.
//    128 threads/block, 32 nodes/block; W1 in dynamic smem (64KB) +
//    4-node transposed tile (2KB)
// ---------------------------------------------------------------------------
__global__ void gemm1_kernel(const float* __restrict__ W1,
                             const float* __restrict__ b1, int n) {
    extern __shared__ float sh[];
    float* shW  = sh;               // [128][128]
    float* shHT = sh + 128 * 128;   // [128][4] transposed tile
    int tid = threadIdx.x;

    for (int i = tid; i < 128 * 128; i += 128) shW[i] = W1[i];
    float bj = b1[tid];
    int base = blockIdx.x * 32;
    __syncthreads();

    for (int g = 0; g < 8; g++) {
        int nb = base + g * 4;
        #pragma unroll
        for (int nn = 0; nn < 4; nn++) {
            int node = nb + nn;
            shHT[tid * 4 + nn] =
                (node < n) ? g_hin[(size_t)node * 128 + tid] : 0.0f;
        }
        __syncthreads();

        float a0 = bj, a1 = bj, a2 = bj, a3 = bj;
        #pragma unroll
        for (int k = 0; k < 128; k++) {
            float4 hv = reinterpret_cast<float4*>(shHT)[k];
            float  w  = shW[k * 128 + tid];
            a0 = fmaf(hv.x, w, a0);
            a1 = fmaf(hv.y, w, a1);
            a2 = fmaf(hv.z, w, a2);
            a3 = fmaf(hv.w, w, a3);
        }
        if (nb + 0 < n) g_h1[(size_t)(nb + 0) * 128 + tid] = fmaxf(a0, 0.f);
        if (nb + 1 < n) g_h1[(size_t)(nb + 1) * 128 + tid] = fmaxf(a1, 0.f);
        if (nb + 2 < n) g_h1[(size_t)(nb + 2) * 128 + tid] = fmaxf(a2, 0.f);
        if (nb + 3 < n) g_h1[(size_t)(nb + 3) * 128 + tid] = fmaxf(a3, 0.f);
        __syncthreads();
    }
}

// ---------------------------------------------------------------------------
// 7) xw = h1 @ W2 (no bias). 320 threads/block, 32 nodes/block.
//    thread t -> (node s=t/10, output quad j4=t%10); 1 LDS + 1 LDS.128 + 4 FMA
// ---------------------------------------------------------------------------
__global__ void gemm2_kernel(const float* __restrict__ W2, int n) {
    __shared__ float shW[128 * 40];     // 20KB
    __shared__ float shH[32 * 128];     // 16KB
    int tid = threadIdx.x;

    for (int i = tid; i < 128 * 40; i += 320) shW[i] = W2[i];

    int base = blockIdx.x * 32;
    for (int i = tid; i < 32 * 128; i += 320) {
        int node = base + (i >> 7);
        shH[i] = (node < n) ? g_h1[(size_t)node * 128 + (i & 127)] : 0.0f;
    }
    __syncthreads();

    int s  = tid / 10;
    int j4 = tid - s * 10;
    int node = base + s;

    float4 acc = make_float4(0.f, 0.f, 0.f, 0.f);
    #pragma unroll
    for (int k = 0; k < 128; k++) {
        float  h  = shH[s * 128 + k];
        float4 w4 = reinterpret_cast<float4*>(shW)[k * 10 + j4];
        acc.x = fmaf(h, w4.x, acc.x);
        acc.y = fmaf(h, w4.y, acc.y);
        acc.z = fmaf(h, w4.z, acc.z);
        acc.w = fmaf(h, w4.w, acc.w);
    }
    if (node < n)
        reinterpret_cast<float4*>(g_xw)[(size_t)node * 10 + j4] = acc;
}

// ---------------------------------------------------------------------------
// 8) GCN gather + self-loop + bias: 320 threads/block, 32 nodes/block,
//    thread -> (node, float4 chunk p). Single write, no atomics.
// ---------------------------------------------------------------------------
__global__ void gather2_kernel(const float* __restrict__ b2,
                               float* __restrict__ out, int n) {
    __shared__ float shB[40];
    int tid = threadIdx.x;
    if (tid < 40) shB[tid] = b2[tid];
    __syncthreads();

    int s = tid / 10;
    int p = tid - s * 10;
    int node = blockIdx.x * 32 + s;
    if (node >= n) return;

    float dr = g_dinv[node];
    int a = g_rowptr[node];
    int b = g_rowptr[node + 1];

    float4 acc = make_float4(0.f, 0.f, 0.f, 0.f);
    for (int j = a; j < b; j++) {
        int c = g_scol[j];
        float  dc = g_dinv[c];
        float4 v  = reinterpret_cast<const float4*>(g_xw)[(size_t)c * 10 + p];
        acc.x = fmaf(v.x, dc, acc.x);
        acc.y = fmaf(v.y, dc, acc.y);
        acc.z = fmaf(v.z, dc, acc.z);
        acc.w = fmaf(v.w, dc, acc.w);
    }

    float4 self = reinterpret_cast<const float4*>(g_xw)[(size_t)node * 10 + p];
    float d2 = dr * dr;
    float4 o;
    o.x = fmaf(acc.x, dr, fmaf(self.x, d2, shB[p * 4 + 0]));
    o.y = fmaf(acc.y, dr, fmaf(self.y, d2, shB[p * 4 + 1]));
    o.z = fmaf(acc.z, dr, fmaf(self.z, d2, shB[p * 4 + 2]));
    o.w = fmaf(acc.w, dr, fmaf(self.w, d2, shB[p * 4 + 3]));
    reinterpret_cast<float4*>(out)[(size_t)node * 10 + p] = o;
}

// ---------------------------------------------------------------------------
// 9) in-place row log_softmax (one warp per node, 40 cols)
// ---------------------------------------------------------------------------
__global__ void lsm_kernel(float* __restrict__ out, int n) {
    int warp = (blockIdx.x * blockDim.x + threadIdx.x) >> 5;
    int lane = threadIdx.x & 31;
    if (warp >= n) return;
    size_t base = (size_t)warp * NC;

    float v0 = out[base + lane];
    float v1 = (lane < NC - 32) ? out[base + 32 + lane] : -INFINITY;

    float m = fmaxf(v0, v1);
    #pragma unroll
    for (int o = 16; o > 0; o >>= 1)
        m = fmaxf(m, __shfl_xor_sync(0xffffffffu, m, o));

    float s = expf(v0 - m) + ((lane < NC - 32) ? expf(v1 - m) : 0.0f);
    #pragma unroll
    for (int o = 16; o > 0; o >>= 1)
        s += __shfl_xor_sync(0xffffffffu, s, o);

    float lse = logf(s);
    out[base + lane] = v0 - m - lse;
    if (lane < NC - 32) out[base + 32 + lane] = v1 - m - lse;
}

// ---------------------------------------------------------------------------
extern "C" void kernel_launch(void* const* d_in, const int* in_sizes, int n_in,
                              void* d_out, int out_size) {
    const float*        x    = (const float*)d_in[0];
    const unsigned int* mask = (const unsigned int*)d_in[1];
    const int*          eidx = (const int*)d_in[2];
    const float*        W1   = (const float*)d_in[3];
    const float*        b1   = (const float*)d_in[4];
    const float*        W2   = (const float*)d_in[5];
    const float*        b2   = (const float*)d_in[6];
    float* out = (float*)d_out;

    const int N = in_sizes[0] / DF;   // 100000
    const int E = in_sizes[2] / 2;    // 1600000
    const int* row = eidx;
    const int* col = eidx + E;

    zero_kernel<<<(NN + 255) / 256, 256>>>();
    prep_kernel<<<(N * 32 + 255) / 256, 256>>>(x, mask, N);
    hist_kernel<<<(E + 255) / 256, 256>>>(row, E);
    scan_kernel<<<1, 1024>>>();
    edges_kernel<<<(E + 255) / 256, 256>>>(row, col, E);
    agg1_kernel<<<(N + 7) / 8, 256>>>(N);

    {
        int smem = (128 * 128 + 128 * 4) * (int)sizeof(float);
        cudaFuncSetAttribute(gemm1_kernel,
                             cudaFuncAttributeMaxDynamicSharedMemorySize, smem);
        gemm1_kernel<<<(N + 31) / 32, 128, smem>>>(W1, b1, N);
    }

    gemm2_kernel<<<(N + 31) / 32, 320>>>(W2, N);
    gather2_kernel<<<(N + 31) / 32, 320>>>(b2, out, N);
    lsm_kernel<<<(N + 7) / 8, 256>>>(out, N);
}

// round 4
// speedup vs baseline: 1.8637x; 1.3434x over previous
#include <cuda_runtime.h>
#include <math.h>

// PaGNN: N=100000 nodes, E=1600000 edges, D=128, H=128, C=40
#define NN 100000
#define DF 128
#define NC 40

#define SCAN_CHUNK 1024                     // elements per scan block
#define SCAN_NB ((NN + SCAN_CHUNK - 1) / SCAN_CHUNK)   // 98

// ---- scratch (device globals; no runtime allocation allowed) ---------------
__device__ float g_xm   [NN * DF];     // x * mask (pre-masked features)
__device__ uint4 g_mbits[NN];          // 128-bit mask per node (ballot layout)
__device__ float g_hin  [NN * DF];     // normalized aggregation (conv1 input)
__device__ float g_h1   [NN * DF];     // relu(conv1)
__device__ float g_xw   [NN * NC];     // (h1 @ W2) * dinv[node]  (pre-scaled)
__device__ int   g_rowcnt[NN];         // in-degree histogram
__device__ int   g_rowptr[NN + 1];     // CSR row pointers
__device__ int   g_wpos [NN];          // running write positions for bucket fill
__device__ int   g_scol [2000000];     // CSR column indices (cap > E)
__device__ float g_dinv [NN];          // rsqrt(deg+1)
__device__ int   g_bsum [SCAN_NB];     // scan phase A block sums
__device__ int   g_boff [SCAN_NB];     // scan phase B exclusive offsets

// ---------------------------------------------------------------------------
// 0) zero the histogram
// ---------------------------------------------------------------------------
__global__ void zero_kernel() {
    int i = blockIdx.x * blockDim.x + threadIdx.x;
    if (i < NN) g_rowcnt[i] = 0;
}

// ---------------------------------------------------------------------------
// 1) prep: xm = x*mask, 128-bit mask bitmap per node (ballot layout:
//    word i bit `lane` = mask[node][4*lane + i]); one warp per node
// ---------------------------------------------------------------------------
__global__ void prep_kernel(const float* __restrict__ x,
                            const unsigned int* __restrict__ mask,
                            int n) {
    int node = (blockIdx.x * blockDim.x + threadIdx.x) >> 5;
    int lane = threadIdx.x & 31;
    if (node >= n) return;

    float4 xv = reinterpret_cast<const float4*>(x)[(size_t)node * 32 + lane];
    uint4  mv = reinterpret_cast<const uint4*>(mask)[(size_t)node * 32 + lane];

    float4 xm;
    xm.x = mv.x ? xv.x : 0.0f;
    xm.y = mv.y ? xv.y : 0.0f;
    xm.z = mv.z ? xv.z : 0.0f;
    xm.w = mv.w ? xv.w : 0.0f;
    reinterpret_cast<float4*>(g_xm)[(size_t)node * 32 + lane] = xm;

    unsigned b0 = __ballot_sync(0xffffffffu, mv.x != 0u);
    unsigned b1 = __ballot_sync(0xffffffffu, mv.y != 0u);
    unsigned b2 = __ballot_sync(0xffffffffu, mv.z != 0u);
    unsigned b3 = __ballot_sync(0xffffffffu, mv.w != 0u);
    if (lane == 0) g_mbits[node] = make_uint4(b0, b1, b2, b3);
}

// ---------------------------------------------------------------------------
// 2) histogram of destination rows
// ---------------------------------------------------------------------------
__global__ void hist_kernel(const int* __restrict__ row, int E) {
    int e = blockIdx.x * blockDim.x + threadIdx.x;
    if (e < E) atomicAdd(&g_rowcnt[row[e]], 1);
}

// ---------------------------------------------------------------------------
// 3a) scan phase A: per-block sums (256 thr x 4 elems = 1024 per block)
// ---------------------------------------------------------------------------
__global__ void scanA_kernel() {
    __shared__ int swarp[8];
    int tid = threadIdx.x;
    int base = blockIdx.x * SCAN_CHUNK + tid * 4;

    int s = 0;
    #pragma unroll
    for (int k = 0; k < 4; k++) {
        int i = base + k;
        if (i < NN) s += g_rowcnt[i];
    }
    #pragma unroll
    for (int o = 16; o > 0; o >>= 1)
        s += __shfl_xor_sync(0xffffffffu, s, o);
    if ((tid & 31) == 0) swarp[tid >> 5] = s;
    __syncthreads();
    if (tid < 8) {
        int v = swarp[tid];
        #pragma unroll
        for (int o = 4; o > 0; o >>= 1)
            v += __shfl_xor_sync(0xffu, v, o);
        if (tid == 0) g_bsum[blockIdx.x] = v;
    }
}

// ---------------------------------------------------------------------------
// 3b) scan phase B: exclusive scan of the 98 block sums (one small block)
// ---------------------------------------------------------------------------
__global__ void scanB_kernel() {
    __shared__ int sh[128];
    int tid = threadIdx.x;
    int v = (tid < SCAN_NB) ? g_bsum[tid] : 0;
    sh[tid] = v;
    __syncthreads();
    for (int off = 1; off < 128; off <<= 1) {
        int u = (tid >= off) ? sh[tid - off] : 0;
        __syncthreads();
        sh[tid] += u;
        __syncthreads();
    }
    if (tid < SCAN_NB) g_boff[tid] = sh[tid] - v;   // exclusive
    if (tid == SCAN_NB - 1) g_rowptr[NN] = sh[tid];
}

// ---------------------------------------------------------------------------
// 3c) scan phase C: intra-block exclusive scan + block offset; emits
//     rowptr, wpos, dinv
// ---------------------------------------------------------------------------
__global__ void scanC_kernel() {
    __shared__ int sh[256];
    int tid = threadIdx.x;
    int base = blockIdx.x * SCAN_CHUNK + tid * 4;

    int c[4];
    int s = 0;
    #pragma unroll
    for (int k = 0; k < 4; k++) {
        int i = base + k;
        c[k] = (i < NN) ? g_rowcnt[i] : 0;
        s += c[k];
    }
    sh[tid] = s;
    __syncthreads();
    for (int off = 1; off < 256; off <<= 1) {
        int u = (tid >= off) ? sh[tid - off] : 0;
        __syncthreads();
        sh[tid] += u;
        __syncthreads();
    }

    int prefix = g_boff[blockIdx.x] + sh[tid] - s;   // exclusive for elem base
    #pragma unroll
    for (int k = 0; k < 4; k++) {
        int i = base + k;
        if (i < NN) {
            g_rowptr[i] = prefix;
            g_wpos[i]   = prefix;
            g_dinv[i]   = rsqrtf((float)c[k] + 1.0f);
            prefix += c[k];
        }
    }
}

// ---------------------------------------------------------------------------
// 4) bucket-fill CSR columns
// ---------------------------------------------------------------------------
__global__ void edges_kernel(const int* __restrict__ row,
                             const int* __restrict__ col, int E) {
    int e = blockIdx.x * blockDim.x + threadIdx.x;
    if (e >= E) return;
    int p = atomicAdd(&g_wpos[row[e]], 1);
    g_scol[p] = col[e];
}

// ---------------------------------------------------------------------------
// 5) pass-1 aggregation (gather): one warp per node, 4 feats/lane.
//    hin = (sum_{c in N(r)} xm[c]) / max(count_per_feat, 1)
// ---------------------------------------------------------------------------
__global__ void agg1_kernel(int n) {
    int node = (blockIdx.x * blockDim.x + threadIdx.x) >> 5;
    int lane = threadIdx.x & 31;
    if (node >= n) return;

    int s = g_rowptr[node];
    int e = g_rowptr[node + 1];

    float ax = 0.f, ay = 0.f, az = 0.f, aw = 0.f;
    int   cx = 0,   cy = 0,   cz = 0,   cw = 0;

    for (int j = s; j < e; j++) {
        int c = g_scol[j];
        float4 v  = reinterpret_cast<const float4*>(g_xm)[(size_t)c * 32 + lane];
        uint4  bw = g_mbits[c];
        ax += v.x; ay += v.y; az += v.z; aw += v.w;
        cx += (bw.x >> lane) & 1u;
        cy += (bw.y >> lane) & 1u;
        cz += (bw.z >> lane) & 1u;
        cw += (bw.w >> lane) & 1u;
    }

    float4 h;
    h.x = ax / fmaxf((float)cx, 1.0f);
    h.y = ay / fmaxf((float)cy, 1.0f);
    h.z = az / fmaxf((float)cz, 1.0f);
    h.w = aw / fmaxf((float)cw, 1.0f);
    reinterpret_cast<float4*>(g_hin)[(size_t)node * 32 + lane] = h;
}

// ---------------------------------------------------------------------------
// 6) h1 = relu(hin @ W1 + b1), register-tiled 4 nodes/thread.
// ---------------------------------------------------------------------------
__global__ void gemm1_kernel(const float* __restrict__ W1,
                             const float* __restrict__ b1, int n) {
    extern __shared__ float sh[];
    float* shW  = sh;               // [128][128]
    float* shHT = sh + 128 * 128;   // [128][4] transposed tile
    int tid = threadIdx.x;

    for (int i = tid; i < 128 * 128; i += 128) shW[i] = W1[i];
    float bj = b1[tid];
    int base = blockIdx.x * 32;
    __syncthreads();

    for (int g = 0; g < 8; g++) {
        int nb = base + g * 4;
        #pragma unroll
        for (int nn = 0; nn < 4; nn++) {
            int node = nb + nn;
            shHT[tid * 4 + nn] =
                (node < n) ? g_hin[(size_t)node * 128 + tid] : 0.0f;
        }
        __syncthreads();

        float a0 = bj, a1 = bj, a2 = bj, a3 = bj;
        #pragma unroll
        for (int k = 0; k < 128; k++) {
            float4 hv = reinterpret_cast<float4*>(shHT)[k];
            float  w  = shW[k * 128 + tid];
            a0 = fmaf(hv.x, w, a0);
            a1 = fmaf(hv.y, w, a1);
            a2 = fmaf(hv.z, w, a2);
            a3 = fmaf(hv.w, w, a3);
        }
        if (nb + 0 < n) g_h1[(size_t)(nb + 0) * 128 + tid] = fmaxf(a0, 0.f);
        if (nb + 1 < n) g_h1[(size_t)(nb + 1) * 128 + tid] = fmaxf(a1, 0.f);
        if (nb + 2 < n) g_h1[(size_t)(nb + 2) * 128 + tid] = fmaxf(a2, 0.f);
        if (nb + 3 < n) g_h1[(size_t)(nb + 3) * 128 + tid] = fmaxf(a3, 0.f);
        __syncthreads();
    }
}

// ---------------------------------------------------------------------------
// 7) xw = (h1 @ W2) * dinv[node]   (pre-scaled for the GCN gather)
//    320 threads/block, 32 nodes/block; thread -> (node, output quad)
// ---------------------------------------------------------------------------
__global__ void gemm2_kernel(const float* __restrict__ W2, int n) {
    __shared__ float shW[128 * 40];     // 20KB
    __shared__ float shH[32 * 128];     // 16KB
    int tid = threadIdx.x;

    for (int i = tid; i < 128 * 40; i += 320) shW[i] = W2[i];

    int base = blockIdx.x * 32;
    for (int i = tid; i < 32 * 128; i += 320) {
        int node = base + (i >> 7);
        shH[i] = (node < n) ? g_h1[(size_t)node * 128 + (i & 127)] : 0.0f;
    }
    __syncthreads();

    int s  = tid / 10;
    int j4 = tid - s * 10;
    int node = base + s;
    if (node >= n) return;

    float4 acc = make_float4(0.f, 0.f, 0.f, 0.f);
    #pragma unroll
    for (int k = 0; k < 128; k++) {
        float  h  = shH[s * 128 + k];
        float4 w4 = reinterpret_cast<float4*>(shW)[k * 10 + j4];
        acc.x = fmaf(h, w4.x, acc.x);
        acc.y = fmaf(h, w4.y, acc.y);
        acc.z = fmaf(h, w4.z, acc.z);
        acc.w = fmaf(h, w4.w, acc.w);
    }
    float dc = g_dinv[node];
    acc.x *= dc; acc.y *= dc; acc.z *= dc; acc.w *= dc;
    reinterpret_cast<float4*>(g_xw)[(size_t)node * 10 + j4] = acc;
}

// ---------------------------------------------------------------------------
// 8) GCN gather + self-loop + bias (xw pre-scaled by dinv[col]):
//    out = dr * (sum_c xw_s[c] + xw_s[node]) + b
// ---------------------------------------------------------------------------
__global__ void gather2_kernel(const float* __restrict__ b2,
                               float* __restrict__ out, int n) {
    __shared__ float shB[40];
    int tid = threadIdx.x;
    if (tid < 40) shB[tid] = b2[tid];
    __syncthreads();

    int s = tid / 10;
    int p = tid - s * 10;
    int node = blockIdx.x * 32 + s;
    if (node >= n) return;

    float dr = g_dinv[node];
    int a = g_rowptr[node];
    int b = g_rowptr[node + 1];

    float4 acc = reinterpret_cast<const float4*>(g_xw)[(size_t)node * 10 + p];
    for (int j = a; j < b; j++) {
        int c = g_scol[j];
        float4 v = reinterpret_cast<const float4*>(g_xw)[(size_t)c * 10 + p];
        acc.x += v.x; acc.y += v.y; acc.z += v.z; acc.w += v.w;
    }

    float4 o;
    o.x = fmaf(acc.x, dr, shB[p * 4 + 0]);
    o.y = fmaf(acc.y, dr, shB[p * 4 + 1]);
    o.z = fmaf(acc.z, dr, shB[p * 4 + 2]);
    o.w = fmaf(acc.w, dr, shB[p * 4 + 3]);
    reinterpret_cast<float4*>(out)[(size_t)node * 10 + p] = o;
}

// ---------------------------------------------------------------------------
// 9) in-place row log_softmax (one warp per node, 40 cols)
// ---------------------------------------------------------------------------
__global__ void lsm_kernel(float* __restrict__ out, int n) {
    int warp = (blockIdx.x * blockDim.x + threadIdx.x) >> 5;
    int lane = threadIdx.x & 31;
    if (warp >= n) return;
    size_t base = (size_t)warp * NC;

    float v0 = out[base + lane];
    float v1 = (lane < NC - 32) ? out[base + 32 + lane] : -INFINITY;

    float m = fmaxf(v0, v1);
    #pragma unroll
    for (int o = 16; o > 0; o >>= 1)
        m = fmaxf(m, __shfl_xor_sync(0xffffffffu, m, o));

    float s = expf(v0 - m) + ((lane < NC - 32) ? expf(v1 - m) : 0.0f);
    #pragma unroll
    for (int o = 16; o > 0; o >>= 1)
        s += __shfl_xor_sync(0xffffffffu, s, o);

    float lse = logf(s);
    out[base + lane] = v0 - m - lse;
    if (lane < NC - 32) out[base + 32 + lane] = v1 - m - lse;
}

// ---------------------------------------------------------------------------
extern "C" void kernel_launch(void* const* d_in, const int* in_sizes, int n_in,
                              void* d_out, int out_size) {
    const float*        x    = (const float*)d_in[0];
    const unsigned int* mask = (const unsigned int*)d_in[1];
    const int*          eidx = (const int*)d_in[2];
    const float*        W1   = (const float*)d_in[3];
    const float*        b1   = (const float*)d_in[4];
    const float*        W2   = (const float*)d_in[5];
    const float*        b2   = (const float*)d_in[6];
    float* out = (float*)d_out;

    const int N = in_sizes[0] / DF;   // 100000
    const int E = in_sizes[2] / 2;    // 1600000
    const int* row = eidx;
    const int* col = eidx + E;

    zero_kernel<<<(NN + 255) / 256, 256>>>();
    prep_kernel<<<(N * 32 + 255) / 256, 256>>>(x, mask, N);
    hist_kernel<<<(E + 255) / 256, 256>>>(row, E);
    scanA_kernel<<<SCAN_NB, 256>>>();
    scanB_kernel<<<1, 128>>>();
    scanC_kernel<<<SCAN_NB, 256>>>();
    edges_kernel<<<(E + 255) / 256, 256>>>(row, col, E);
    agg1_kernel<<<(N + 7) / 8, 256>>>(N);

    {
        int smem = (128 * 128 + 128 * 4) * (int)sizeof(float);
        cudaFuncSetAttribute(gemm1_kernel,
                             cudaFuncAttributeMaxDynamicSharedMemorySize, smem);
        gemm1_kernel<<<(N + 31) / 32, 128, smem>>>(W1, b1, N);
    }

    gemm2_kernel<<<(N + 31) / 32, 320>>>(W2, N);
    gather2_kernel<<<(N + 31) / 32, 320>>>(b2, out, N);
    lsm_kernel<<<(N + 7) / 8, 256>>>(out, N);
}

// round 5
// speedup vs baseline: 2.1398x; 1.1481x over previous
#include <cuda_runtime.h>
#include <math.h>

// PaGNN: N=100000 nodes, E=1600000 edges, D=128, H=128, C=40
#define NN 100000
#define DF 128
#define NC 40

#define SCAN_CHUNK 1024
#define SCAN_NB ((NN + SCAN_CHUNK - 1) / SCAN_CHUNK)   // 98

typedef unsigned long long ull;

// ---- scratch (device globals; no runtime allocation allowed) ---------------
__device__ float g_xm   [NN * DF];     // x * mask
__device__ uint4 g_mbits[NN];          // 128-bit mask per node (ballot layout)
__device__ float g_hin  [NN * DF];     // normalized aggregation (conv1 input)
__device__ float g_h1   [NN * DF];     // relu(conv1)
__device__ float g_xw   [NN * NC];     // (h1 @ W2) * dinv[node]
__device__ int   g_rowcnt[NN];
__device__ int   g_rowptr[NN + 1];
__device__ int   g_wpos [NN];
__device__ int   g_scol [2000000];
__device__ float g_dinv [NN];
__device__ int   g_bsum [SCAN_NB];
__device__ int   g_boff [SCAN_NB];

// ---- f32x2 helpers ----------------------------------------------------------
__device__ __forceinline__ ull pack2(float v) {
    ull r;
    unsigned u = __float_as_uint(v);
    asm("mov.b64 %0, {%1, %2};" : "=l"(r) : "r"(u), "r"(u));
    return r;
}
__device__ __forceinline__ void ffma2(ull& acc, ull a, ull b) {
    asm("fma.rn.f32x2 %0, %1, %2, %0;" : "+l"(acc) : "l"(a), "l"(b));
}
__device__ __forceinline__ void unpack2(ull v, float& lo, float& hi) {
    unsigned a, b;
    asm("mov.b64 {%0, %1}, %2;" : "=r"(a), "=r"(b) : "l"(v));
    lo = __uint_as_float(a);
    hi = __uint_as_float(b);
}

// ---------------------------------------------------------------------------
// 0) zero the histogram
// ---------------------------------------------------------------------------
__global__ void zero_kernel() {
    int i = blockIdx.x * blockDim.x + threadIdx.x;
    if (i < NN) g_rowcnt[i] = 0;
}

// ---------------------------------------------------------------------------
// 1) prep: xm = x*mask + 128-bit mask bitmap; one warp per node
// ---------------------------------------------------------------------------
__global__ void prep_kernel(const float* __restrict__ x,
                            const unsigned int* __restrict__ mask,
                            int n) {
    int node = (blockIdx.x * blockDim.x + threadIdx.x) >> 5;
    int lane = threadIdx.x & 31;
    if (node >= n) return;

    float4 xv = reinterpret_cast<const float4*>(x)[(size_t)node * 32 + lane];
    uint4  mv = reinterpret_cast<const uint4*>(mask)[(size_t)node * 32 + lane];

    float4 xm;
    xm.x = mv.x ? xv.x : 0.0f;
    xm.y = mv.y ? xv.y : 0.0f;
    xm.z = mv.z ? xv.z : 0.0f;
    xm.w = mv.w ? xv.w : 0.0f;
    reinterpret_cast<float4*>(g_xm)[(size_t)node * 32 + lane] = xm;

    unsigned b0 = __ballot_sync(0xffffffffu, mv.x != 0u);
    unsigned b1 = __ballot_sync(0xffffffffu, mv.y != 0u);
    unsigned b2 = __ballot_sync(0xffffffffu, mv.z != 0u);
    unsigned b3 = __ballot_sync(0xffffffffu, mv.w != 0u);
    if (lane == 0) g_mbits[node] = make_uint4(b0, b1, b2, b3);
}

// ---------------------------------------------------------------------------
// 2) histogram of destination rows
// ---------------------------------------------------------------------------
__global__ void hist_kernel(const int* __restrict__ row, int E) {
    int e = blockIdx.x * blockDim.x + threadIdx.x;
    if (e < E) atomicAdd(&g_rowcnt[row[e]], 1);
}

// ---------------------------------------------------------------------------
// 3) three-phase scan
// ---------------------------------------------------------------------------
__global__ void scanA_kernel() {
    __shared__ int swarp[8];
    int tid = threadIdx.x;
    int base = blockIdx.x * SCAN_CHUNK + tid * 4;

    int s = 0;
    #pragma unroll
    for (int k = 0; k < 4; k++) {
        int i = base + k;
        if (i < NN) s += g_rowcnt[i];
    }
    #pragma unroll
    for (int o = 16; o > 0; o >>= 1)
        s += __shfl_xor_sync(0xffffffffu, s, o);
    if ((tid & 31) == 0) swarp[tid >> 5] = s;
    __syncthreads();
    if (tid < 8) {
        int v = swarp[tid];
        #pragma unroll
        for (int o = 4; o > 0; o >>= 1)
            v += __shfl_xor_sync(0xffu, v, o);
        if (tid == 0) g_bsum[blockIdx.x] = v;
    }
}

__global__ void scanB_kernel() {
    __shared__ int sh[128];
    int tid = threadIdx.x;
    int v = (tid < SCAN_NB) ? g_bsum[tid] : 0;
    sh[tid] = v;
    __syncthreads();
    for (int off = 1; off < 128; off <<= 1) {
        int u = (tid >= off) ? sh[tid - off] : 0;
        __syncthreads();
        sh[tid] += u;
        __syncthreads();
    }
    if (tid < SCAN_NB) g_boff[tid] = sh[tid] - v;
    if (tid == SCAN_NB - 1) g_rowptr[NN] = sh[tid];
}

__global__ void scanC_kernel() {
    __shared__ int sh[256];
    int tid = threadIdx.x;
    int base = blockIdx.x * SCAN_CHUNK + tid * 4;

    int c[4];
    int s = 0;
    #pragma unroll
    for (int k = 0; k < 4; k++) {
        int i = base + k;
        c[k] = (i < NN) ? g_rowcnt[i] : 0;
        s += c[k];
    }
    sh[tid] = s;
    __syncthreads();
    for (int off = 1; off < 256; off <<= 1) {
        int u = (tid >= off) ? sh[tid - off] : 0;
        __syncthreads();
        sh[tid] += u;
        __syncthreads();
    }

    int prefix = g_boff[blockIdx.x] + sh[tid] - s;
    #pragma unroll
    for (int k = 0; k < 4; k++) {
        int i = base + k;
        if (i < NN) {
            g_rowptr[i] = prefix;
            g_wpos[i]   = prefix;
            g_dinv[i]   = rsqrtf((float)c[k] + 1.0f);
            prefix += c[k];
        }
    }
}

// ---------------------------------------------------------------------------
// 4) bucket-fill CSR columns
// ---------------------------------------------------------------------------
__global__ void edges_kernel(const int* __restrict__ row,
                             const int* __restrict__ col, int E) {
    int e = blockIdx.x * blockDim.x + threadIdx.x;
    if (e >= E) return;
    int p = atomicAdd(&g_wpos[row[e]], 1);
    g_scol[p] = col[e];
}

// ---------------------------------------------------------------------------
// 5) pass-1 aggregation (gather): one warp per node, 4 feats/lane
// ---------------------------------------------------------------------------
__global__ void agg1_kernel(int n) {
    int node = (blockIdx.x * blockDim.x + threadIdx.x) >> 5;
    int lane = threadIdx.x & 31;
    if (node >= n) return;

    int s = g_rowptr[node];
    int e = g_rowptr[node + 1];

    float ax = 0.f, ay = 0.f, az = 0.f, aw = 0.f;
    int   cx = 0,   cy = 0,   cz = 0,   cw = 0;

    for (int j = s; j < e; j++) {
        int c = g_scol[j];
        float4 v  = reinterpret_cast<const float4*>(g_xm)[(size_t)c * 32 + lane];
        uint4  bw = g_mbits[c];
        ax += v.x; ay += v.y; az += v.z; aw += v.w;
        cx += (bw.x >> lane) & 1u;
        cy += (bw.y >> lane) & 1u;
        cz += (bw.z >> lane) & 1u;
        cw += (bw.w >> lane) & 1u;
    }

    float4 h;
    h.x = ax / fmaxf((float)cx, 1.0f);
    h.y = ay / fmaxf((float)cy, 1.0f);
    h.z = az / fmaxf((float)cz, 1.0f);
    h.w = aw / fmaxf((float)cw, 1.0f);
    reinterpret_cast<float4*>(g_hin)[(size_t)node * 32 + lane] = h;
}

// ---------------------------------------------------------------------------
// 6) h1 = relu(hin @ W1 + b1): 8-node register tile, packed f32x2 FMA.
//    128 threads (tid = output col), 32 nodes/block.
// ---------------------------------------------------------------------------
__global__ void gemm1_kernel(const float* __restrict__ W1,
                             const float* __restrict__ b1, int n) {
    extern __shared__ float sh[];
    float* shW  = sh;               // [128][128]  64KB
    float* shHT = sh + 128 * 128;   // [128][8]    4KB (transposed 8-node tile)
    int tid = threadIdx.x;

    for (int i = tid; i < 128 * 128; i += 128) shW[i] = W1[i];
    ull bb = pack2(b1[tid]);
    int base = blockIdx.x * 32;
    __syncthreads();

    for (int g = 0; g < 4; g++) {
        int nb = base + g * 8;
        {
            float t[8];
            #pragma unroll
            for (int nn = 0; nn < 8; nn++) {
                int node = nb + nn;
                t[nn] = (node < n) ? g_hin[(size_t)node * 128 + tid] : 0.0f;
            }
            reinterpret_cast<float4*>(shHT + tid * 8)[0] =
                make_float4(t[0], t[1], t[2], t[3]);
            reinterpret_cast<float4*>(shHT + tid * 8)[1] =
                make_float4(t[4], t[5], t[6], t[7]);
        }
        __syncthreads();

        ull a01 = bb, a23 = bb, a45 = bb, a67 = bb;
        #pragma unroll
        for (int k = 0; k < 128; k++) {
            ulonglong2 p0 = reinterpret_cast<const ulonglong2*>(shHT + k * 8)[0];
            ulonglong2 p1 = reinterpret_cast<const ulonglong2*>(shHT + k * 8)[1];
            ull ww = pack2(shW[k * 128 + tid]);
            ffma2(a01, p0.x, ww);
            ffma2(a23, p0.y, ww);
            ffma2(a45, p1.x, ww);
            ffma2(a67, p1.y, ww);
        }

        float v[8];
        unpack2(a01, v[0], v[1]);
        unpack2(a23, v[2], v[3]);
        unpack2(a45, v[4], v[5]);
        unpack2(a67, v[6], v[7]);
        #pragma unroll
        for (int nn = 0; nn < 8; nn++) {
            int node = nb + nn;
            if (node < n)
                g_h1[(size_t)node * 128 + tid] = fmaxf(v[nn], 0.0f);
        }
        __syncthreads();
    }
}

// ---------------------------------------------------------------------------
// 7) xw = (h1 @ W2) * dinv[node]: 320 threads, 32 nodes/block,
//    thread -> (node s, quad j4); padded shH (pitch 132) kills bank conflicts
// ---------------------------------------------------------------------------
#define HP 132
__global__ void gemm2_kernel(const float* __restrict__ W2, int n) {
    __shared__ float shW[128 * 40];     // 20KB
    __shared__ float shH[32 * HP];      // ~16.5KB
    int tid = threadIdx.x;

    for (int i = tid; i < 128 * 40; i += 320) shW[i] = W2[i];

    int base = blockIdx.x * 32;
    for (int i = tid; i < 32 * 128; i += 320) {
        int s  = i >> 7;
        int kk = i & 127;
        int node = base + s;
        shH[s * HP + kk] = (node < n) ? g_h1[(size_t)node * 128 + kk] : 0.0f;
    }
    __syncthreads();

    int s  = tid / 10;
    int j4 = tid - s * 10;
    int node = base + s;
    if (node >= n) return;

    ull a01 = 0, a23 = 0;   // cols j4*4 .. j4*4+3
    #pragma unroll
    for (int k = 0; k < 128; k++) {
        ull hh = pack2(shH[s * HP + k]);
        ulonglong2 w =
            *reinterpret_cast<const ulonglong2*>(shW + k * 40 + j4 * 4);
        ffma2(a01, hh, w.x);
        ffma2(a23, hh, w.y);
    }

    float dc = g_dinv[node];
    float4 o;
    unpack2(a01, o.x, o.y);
    unpack2(a23, o.z, o.w);
    o.x *= dc; o.y *= dc; o.z *= dc; o.w *= dc;
    reinterpret_cast<float4*>(g_xw)[(size_t)node * 10 + j4] = o;
}

// ---------------------------------------------------------------------------
// 8) fused GCN gather + self-loop + bias + log_softmax.
//    320 threads, 32 nodes/block, thread -> (node s, quad p).
//    No early returns (block-wide reductions need all threads).
// ---------------------------------------------------------------------------
__global__ void gather2_lsm_kernel(const float* __restrict__ b2,
                                   float* __restrict__ out, int n) {
    __shared__ float shB[40];
    __shared__ float shV[320];
    __shared__ float shM[32];
    __shared__ float shL[32];
    int tid = threadIdx.x;
    if (tid < 40) shB[tid] = b2[tid];
    __syncthreads();

    int s = tid / 10;
    int p = tid - s * 10;
    int node = blockIdx.x * 32 + s;
    bool live = (node < n);

    float4 o = make_float4(0.f, 0.f, 0.f, 0.f);
    if (live) {
        float dr = g_dinv[node];
        int a = g_rowptr[node];
        int b = g_rowptr[node + 1];

        float4 acc =
            reinterpret_cast<const float4*>(g_xw)[(size_t)node * 10 + p];
        for (int j = a; j < b; j++) {
            int c = g_scol[j];
            float4 v =
                reinterpret_cast<const float4*>(g_xw)[(size_t)c * 10 + p];
            acc.x += v.x; acc.y += v.y; acc.z += v.z; acc.w += v.w;
        }
        o.x = fmaf(acc.x, dr, shB[p * 4 + 0]);
        o.y = fmaf(acc.y, dr, shB[p * 4 + 1]);
        o.z = fmaf(acc.z, dr, shB[p * 4 + 2]);
        o.w = fmaf(acc.w, dr, shB[p * 4 + 3]);
    }

    // row max
    shV[tid] = live ? fmaxf(fmaxf(o.x, o.y), fmaxf(o.z, o.w)) : -INFINITY;
    __syncthreads();
    if (tid < 32) {
        float m = shV[tid * 10];
        #pragma unroll
        for (int i = 1; i < 10; i++) m = fmaxf(m, shV[tid * 10 + i]);
        shM[tid] = m;
    }
    __syncthreads();

    // row sum of exp
    float m = shM[s];
    float le = live ? (expf(o.x - m) + expf(o.y - m) +
                       expf(o.z - m) + expf(o.w - m)) : 0.0f;
    shV[tid] = le;
    __syncthreads();
    if (tid < 32) {
        float su = shV[tid * 10];
        #pragma unroll
        for (int i = 1; i < 10; i++) su += shV[tid * 10 + i];
        shL[tid] = logf(su);
    }
    __syncthreads();

    if (live) {
        float sub = m + shL[s];
        float4 r;
        r.x = o.x - sub; r.y = o.y - sub; r.z = o.z - sub; r.w = o.w - sub;
        reinterpret_cast<float4*>(out)[(size_t)node * 10 + p] = r;
    }
}

// ---------------------------------------------------------------------------
extern "C" void kernel_launch(void* const* d_in, const int* in_sizes, int n_in,
                              void* d_out, int out_size) {
    const float*        x    = (const float*)d_in[0];
    const unsigned int* mask = (const unsigned int*)d_in[1];
    const int*          eidx = (const int*)d_in[2];
    const float*        W1   = (const float*)d_in[3];
    const float*        b1   = (const float*)d_in[4];
    const float*        W2   = (const float*)d_in[5];
    const float*        b2   = (const float*)d_in[6];
    float* out = (float*)d_out;

    const int N = in_sizes[0] / DF;   // 100000
    const int E = in_sizes[2] / 2;    // 1600000
    const int* row = eidx;
    const int* col = eidx + E;

    zero_kernel<<<(NN + 255) / 256, 256>>>();
    prep_kernel<<<(N * 32 + 255) / 256, 256>>>(x, mask, N);
    hist_kernel<<<(E + 255) / 256, 256>>>(row, E);
    scanA_kernel<<<SCAN_NB, 256>>>();
    scanB_kernel<<<1, 128>>>();
    scanC_kernel<<<SCAN_NB, 256>>>();
    edges_kernel<<<(E + 255) / 256, 256>>>(row, col, E);
    agg1_kernel<<<(N + 7) / 8, 256>>>(N);

    {
        int smem = (128 * 128 + 128 * 8) * (int)sizeof(float);
        cudaFuncSetAttribute(gemm1_kernel,
                             cudaFuncAttributeMaxDynamicSharedMemorySize, smem);
        gemm1_kernel<<<(N + 31) / 32, 128, smem>>>(W1, b1, N);
    }

    gemm2_kernel<<<(N + 31) / 32, 320>>>(W2, N);
    gather2_lsm_kernel<<<(N + 31) / 32, 320>>>(b2, out, N);
}

// round 6
// speedup vs baseline: 2.1431x; 1.0015x over previous
#include <cuda_runtime.h>
#include <math.h>

// PaGNN: N=100000 nodes, E=1600000 edges, D=128, H=128, C=40
#define NN 100000
#define DF 128
#define NC 40

#define SCAN_CHUNK 1024
#define SCAN_NB ((NN + SCAN_CHUNK - 1) / SCAN_CHUNK)   // 98

typedef unsigned long long ull;

// ---- scratch (device globals; no runtime allocation allowed) ---------------
__device__ float g_xm   [NN * DF];     // x * mask
__device__ uint4 g_mbits[NN];          // 128-bit mask per node (ballot layout)
__device__ float g_hin  [NN * DF];     // normalized aggregation (conv1 input)
__device__ float g_h1   [NN * DF];     // relu(conv1)
__device__ float g_xw   [NN * NC];     // (h1 @ W2) * dinv[node]
__device__ int   g_rowcnt[NN];
__device__ int   g_rowptr[NN + 1];
__device__ int   g_wpos [NN];
__device__ int   g_scol [2000000];
__device__ float g_dinv [NN];
__device__ int   g_bsum [SCAN_NB];
__device__ int   g_boff [SCAN_NB];

// ---- f32x2 helpers ----------------------------------------------------------
__device__ __forceinline__ ull pack2(float v) {
    ull r;
    unsigned u = __float_as_uint(v);
    asm("mov.b64 %0, {%1, %2};" : "=l"(r) : "r"(u), "r"(u));
    return r;
}
__device__ __forceinline__ void ffma2(ull& acc, ull a, ull b) {
    asm("fma.rn.f32x2 %0, %1, %2, %0;" : "+l"(acc) : "l"(a), "l"(b));
}
__device__ __forceinline__ void unpack2(ull v, float& lo, float& hi) {
    unsigned a, b;
    asm("mov.b64 {%0, %1}, %2;" : "=r"(a), "=r"(b) : "l"(v));
    lo = __uint_as_float(a);
    hi = __uint_as_float(b);
}

// ---------------------------------------------------------------------------
// 0) zero the histogram
// ---------------------------------------------------------------------------
__global__ void zero_kernel() {
    int i = blockIdx.x * blockDim.x + threadIdx.x;
    if (i < NN) g_rowcnt[i] = 0;
}

// ---------------------------------------------------------------------------
// 1) prep: xm = x*mask + 128-bit mask bitmap; one warp per node
// ---------------------------------------------------------------------------
__global__ void prep_kernel(const float* __restrict__ x,
                            const unsigned int* __restrict__ mask,
                            int n) {
    int node = (blockIdx.x * blockDim.x + threadIdx.x) >> 5;
    int lane = threadIdx.x & 31;
    if (node >= n) return;

    float4 xv = reinterpret_cast<const float4*>(x)[(size_t)node * 32 + lane];
    uint4  mv = reinterpret_cast<const uint4*>(mask)[(size_t)node * 32 + lane];

    float4 xm;
    xm.x = mv.x ? xv.x : 0.0f;
    xm.y = mv.y ? xv.y : 0.0f;
    xm.z = mv.z ? xv.z : 0.0f;
    xm.w = mv.w ? xv.w : 0.0f;
    reinterpret_cast<float4*>(g_xm)[(size_t)node * 32 + lane] = xm;

    unsigned b0 = __ballot_sync(0xffffffffu, mv.x != 0u);
    unsigned b1 = __ballot_sync(0xffffffffu, mv.y != 0u);
    unsigned b2 = __ballot_sync(0xffffffffu, mv.z != 0u);
    unsigned b3 = __ballot_sync(0xffffffffu, mv.w != 0u);
    if (lane == 0) g_mbits[node] = make_uint4(b0, b1, b2, b3);
}

// ---------------------------------------------------------------------------
// 2) histogram of destination rows
// ---------------------------------------------------------------------------
__global__ void hist_kernel(const int* __restrict__ row, int E) {
    int e = blockIdx.x * blockDim.x + threadIdx.x;
    if (e < E) atomicAdd(&g_rowcnt[row[e]], 1);
}

// ---------------------------------------------------------------------------
// 3) three-phase scan
// ---------------------------------------------------------------------------
__global__ void scanA_kernel() {
    __shared__ int swarp[8];
    int tid = threadIdx.x;
    int base = blockIdx.x * SCAN_CHUNK + tid * 4;

    int s = 0;
    #pragma unroll
    for (int k = 0; k < 4; k++) {
        int i = base + k;
        if (i < NN) s += g_rowcnt[i];
    }
    #pragma unroll
    for (int o = 16; o > 0; o >>= 1)
        s += __shfl_xor_sync(0xffffffffu, s, o);
    if ((tid & 31) == 0) swarp[tid >> 5] = s;
    __syncthreads();
    if (tid < 8) {
        int v = swarp[tid];
        #pragma unroll
        for (int o = 4; o > 0; o >>= 1)
            v += __shfl_xor_sync(0xffu, v, o);
        if (tid == 0) g_bsum[blockIdx.x] = v;
    }
}

__global__ void scanB_kernel() {
    __shared__ int sh[128];
    int tid = threadIdx.x;
    int v = (tid < SCAN_NB) ? g_bsum[tid] : 0;
    sh[tid] = v;
    __syncthreads();
    for (int off = 1; off < 128; off <<= 1) {
        int u = (tid >= off) ? sh[tid - off] : 0;
        __syncthreads();
        sh[tid] += u;
        __syncthreads();
    }
    if (tid < SCAN_NB) g_boff[tid] = sh[tid] - v;
    if (tid == SCAN_NB - 1) g_rowptr[NN] = sh[tid];
}

__global__ void scanC_kernel() {
    __shared__ int sh[256];
    int tid = threadIdx.x;
    int base = blockIdx.x * SCAN_CHUNK + tid * 4;

    int c[4];
    int s = 0;
    #pragma unroll
    for (int k = 0; k < 4; k++) {
        int i = base + k;
        c[k] = (i < NN) ? g_rowcnt[i] : 0;
        s += c[k];
    }
    sh[tid] = s;
    __syncthreads();
    for (int off = 1; off < 256; off <<= 1) {
        int u = (tid >= off) ? sh[tid - off] : 0;
        __syncthreads();
        sh[tid] += u;
        __syncthreads();
    }

    int prefix = g_boff[blockIdx.x] + sh[tid] - s;
    #pragma unroll
    for (int k = 0; k < 4; k++) {
        int i = base + k;
        if (i < NN) {
            g_rowptr[i] = prefix;
            g_wpos[i]   = prefix;
            g_dinv[i]   = rsqrtf((float)c[k] + 1.0f);
            prefix += c[k];
        }
    }
}

// ---------------------------------------------------------------------------
// 4) bucket-fill CSR columns
// ---------------------------------------------------------------------------
__global__ void edges_kernel(const int* __restrict__ row,
                             const int* __restrict__ col, int E) {
    int e = blockIdx.x * blockDim.x + threadIdx.x;
    if (e >= E) return;
    int p = atomicAdd(&g_wpos[row[e]], 1);
    g_scol[p] = col[e];
}

// ---------------------------------------------------------------------------
// 5) pass-1 aggregation (gather): one warp per node, 4 feats/lane.
//    Unrolled by 4 to raise MLP (4 index + 4 xm + 4 mbits loads in flight).
// ---------------------------------------------------------------------------
__global__ void agg1_kernel(int n) {
    int node = (blockIdx.x * blockDim.x + threadIdx.x) >> 5;
    int lane = threadIdx.x & 31;
    if (node >= n) return;

    int s = g_rowptr[node];
    int e = g_rowptr[node + 1];

    float ax = 0.f, ay = 0.f, az = 0.f, aw = 0.f;
    int   cx = 0,   cy = 0,   cz = 0,   cw = 0;

    const float4* xm4 = reinterpret_cast<const float4*>(g_xm);

    int j = s;
    for (; j + 4 <= e; j += 4) {
        int c0 = g_scol[j + 0];
        int c1 = g_scol[j + 1];
        int c2 = g_scol[j + 2];
        int c3 = g_scol[j + 3];
        float4 v0 = xm4[(size_t)c0 * 32 + lane];
        float4 v1 = xm4[(size_t)c1 * 32 + lane];
        float4 v2 = xm4[(size_t)c2 * 32 + lane];
        float4 v3 = xm4[(size_t)c3 * 32 + lane];
        uint4  b0 = g_mbits[c0];
        uint4  b1 = g_mbits[c1];
        uint4  b2 = g_mbits[c2];
        uint4  b3 = g_mbits[c3];

        ax += v0.x + v1.x + v2.x + v3.x;
        ay += v0.y + v1.y + v2.y + v3.y;
        az += v0.z + v1.z + v2.z + v3.z;
        aw += v0.w + v1.w + v2.w + v3.w;
        cx += ((b0.x >> lane) & 1u) + ((b1.x >> lane) & 1u) +
              ((b2.x >> lane) & 1u) + ((b3.x >> lane) & 1u);
        cy += ((b0.y >> lane) & 1u) + ((b1.y >> lane) & 1u) +
              ((b2.y >> lane) & 1u) + ((b3.y >> lane) & 1u);
        cz += ((b0.z >> lane) & 1u) + ((b1.z >> lane) & 1u) +
              ((b2.z >> lane) & 1u) + ((b3.z >> lane) & 1u);
        cw += ((b0.w >> lane) & 1u) + ((b1.w >> lane) & 1u) +
              ((b2.w >> lane) & 1u) + ((b3.w >> lane) & 1u);
    }
    for (; j < e; j++) {
        int c = g_scol[j];
        float4 v  = xm4[(size_t)c * 32 + lane];
        uint4  bw = g_mbits[c];
        ax += v.x; ay += v.y; az += v.z; aw += v.w;
        cx += (bw.x >> lane) & 1u;
        cy += (bw.y >> lane) & 1u;
        cz += (bw.z >> lane) & 1u;
        cw += (bw.w >> lane) & 1u;
    }

    float4 h;
    h.x = ax / fmaxf((float)cx, 1.0f);
    h.y = ay / fmaxf((float)cy, 1.0f);
    h.z = az / fmaxf((float)cz, 1.0f);
    h.w = aw / fmaxf((float)cw, 1.0f);
    reinterpret_cast<float4*>(g_hin)[(size_t)node * 32 + lane] = h;
}

// ---------------------------------------------------------------------------
// 6) h1 = relu(hin @ W1 + b1): 8-node register tile, packed f32x2 FMA.
//    128 threads (tid = output col), 64 nodes/block (halves W1 refills).
// ---------------------------------------------------------------------------
__global__ void gemm1_kernel(const float* __restrict__ W1,
                             const float* __restrict__ b1, int n) {
    extern __shared__ float sh[];
    float* shW  = sh;               // [128][128]  64KB
    float* shHT = sh + 128 * 128;   // [128][8]    4KB (transposed 8-node tile)
    int tid = threadIdx.x;

    for (int i = tid; i < 128 * 128; i += 128) shW[i] = W1[i];
    ull bb = pack2(b1[tid]);
    int base = blockIdx.x * 64;
    __syncthreads();

    for (int g = 0; g < 8; g++) {
        int nb = base + g * 8;
        {
            float t[8];
            #pragma unroll
            for (int nn = 0; nn < 8; nn++) {
                int node = nb + nn;
                t[nn] = (node < n) ? g_hin[(size_t)node * 128 + tid] : 0.0f;
            }
            reinterpret_cast<float4*>(shHT + tid * 8)[0] =
                make_float4(t[0], t[1], t[2], t[3]);
            reinterpret_cast<float4*>(shHT + tid * 8)[1] =
                make_float4(t[4], t[5], t[6], t[7]);
        }
        __syncthreads();

        ull a01 = bb, a23 = bb, a45 = bb, a67 = bb;
        #pragma unroll
        for (int k = 0; k < 128; k++) {
            ulonglong2 p0 = reinterpret_cast<const ulonglong2*>(shHT + k * 8)[0];
            ulonglong2 p1 = reinterpret_cast<const ulonglong2*>(shHT + k * 8)[1];
            ull ww = pack2(shW[k * 128 + tid]);
            ffma2(a01, p0.x, ww);
            ffma2(a23, p0.y, ww);
            ffma2(a45, p1.x, ww);
            ffma2(a67, p1.y, ww);
        }

        float v[8];
        unpack2(a01, v[0], v[1]);
        unpack2(a23, v[2], v[3]);
        unpack2(a45, v[4], v[5]);
        unpack2(a67, v[6], v[7]);
        #pragma unroll
        for (int nn = 0; nn < 8; nn++) {
            int node = nb + nn;
            if (node < n)
                g_h1[(size_t)node * 128 + tid] = fmaxf(v[nn], 0.0f);
        }
        __syncthreads();
    }
}

// ---------------------------------------------------------------------------
// 7) xw = (h1 @ W2) * dinv[node]: 640 threads, 64 nodes/block,
//    thread -> (node s, quad j4); padded shH (pitch 132) kills bank conflicts
// ---------------------------------------------------------------------------
#define HP 132
__global__ void gemm2_kernel(const float* __restrict__ W2, int n) {
    __shared__ float shW[128 * 40];     // 20KB
    __shared__ float shH[64 * HP];      // ~33KB
    int tid = threadIdx.x;

    for (int i = tid; i < 128 * 40; i += 640) shW[i] = W2[i];

    int base = blockIdx.x * 64;
    for (int i = tid; i < 64 * 128; i += 640) {
        int s  = i >> 7;
        int kk = i & 127;
        int node = base + s;
        shH[s * HP + kk] = (node < n) ? g_h1[(size_t)node * 128 + kk] : 0.0f;
    }
    __syncthreads();

    int s  = tid / 10;
    int j4 = tid - s * 10;
    int node = base + s;
    if (node >= n) return;

    ull a01 = 0, a23 = 0;   // cols j4*4 .. j4*4+3
    #pragma unroll
    for (int k = 0; k < 128; k++) {
        ull hh = pack2(shH[s * HP + k]);
        ulonglong2 w =
            *reinterpret_cast<const ulonglong2*>(shW + k * 40 + j4 * 4);
        ffma2(a01, hh, w.x);
        ffma2(a23, hh, w.y);
    }

    float dc = g_dinv[node];
    float4 o;
    unpack2(a01, o.x, o.y);
    unpack2(a23, o.z, o.w);
    o.x *= dc; o.y *= dc; o.z *= dc; o.w *= dc;
    reinterpret_cast<float4*>(g_xw)[(size_t)node * 10 + j4] = o;
}

// ---------------------------------------------------------------------------
// 8) fused GCN gather + self-loop + bias + log_softmax.
//    320 threads, 32 nodes/block, thread -> (node s, quad p).
//    Gather loop unrolled by 4 for MLP.
// ---------------------------------------------------------------------------
__global__ void gather2_lsm_kernel(const float* __restrict__ b2,
                                   float* __restrict__ out, int n) {
    __shared__ float shB[40];
    __shared__ float shV[320];
    __shared__ float shM[32];
    __shared__ float shL[32];
    int tid = threadIdx.x;
    if (tid < 40) shB[tid] = b2[tid];
    __syncthreads();

    int s = tid / 10;
    int p = tid - s * 10;
    int node = blockIdx.x * 32 + s;
    bool live = (node < n);

    const float4* xw4 = reinterpret_cast<const float4*>(g_xw);

    float4 o = make_float4(0.f, 0.f, 0.f, 0.f);
    if (live) {
        float dr = g_dinv[node];
        int a = g_rowptr[node];
        int b = g_rowptr[node + 1];

        float4 acc = xw4[(size_t)node * 10 + p];
        int j = a;
        for (; j + 4 <= b; j += 4) {
            int c0 = g_scol[j + 0];
            int c1 = g_scol[j + 1];
            int c2 = g_scol[j + 2];
            int c3 = g_scol[j + 3];
            float4 v0 = xw4[(size_t)c0 * 10 + p];
            float4 v1 = xw4[(size_t)c1 * 10 + p];
            float4 v2 = xw4[(size_t)c2 * 10 + p];
            float4 v3 = xw4[(size_t)c3 * 10 + p];
            acc.x += (v0.x + v1.x) + (v2.x + v3.x);
            acc.y += (v0.y + v1.y) + (v2.y + v3.y);
            acc.z += (v0.z + v1.z) + (v2.z + v3.z);
            acc.w += (v0.w + v1.w) + (v2.w + v3.w);
        }
        for (; j < b; j++) {
            int c = g_scol[j];
            float4 v = xw4[(size_t)c * 10 + p];
            acc.x += v.x; acc.y += v.y; acc.z += v.z; acc.w += v.w;
        }
        o.x = fmaf(acc.x, dr, shB[p * 4 + 0]);
        o.y = fmaf(acc.y, dr, shB[p * 4 + 1]);
        o.z = fmaf(acc.z, dr, shB[p * 4 + 2]);
        o.w = fmaf(acc.w, dr, shB[p * 4 + 3]);
    }

    // row max
    shV[tid] = live ? fmaxf(fmaxf(o.x, o.y), fmaxf(o.z, o.w)) : -INFINITY;
    __syncthreads();
    if (tid < 32) {
        float m = shV[tid * 10];
        #pragma unroll
        for (int i = 1; i < 10; i++) m = fmaxf(m, shV[tid * 10 + i]);
        shM[tid] = m;
    }
    __syncthreads();

    // row sum of exp
    float m = shM[s];
    float le = live ? (expf(o.x - m) + expf(o.y - m) +
                       expf(o.z - m) + expf(o.w - m)) : 0.0f;
    shV[tid] = le;
    __syncthreads();
    if (tid < 32) {
        float su = shV[tid * 10];
        #pragma unroll
        for (int i = 1; i < 10; i++) su += shV[tid * 10 + i];
        shL[tid] = logf(su);
    }
    __syncthreads();

    if (live) {
        float sub = m + shL[s];
        float4 r;
        r.x = o.x - sub; r.y = o.y - sub; r.z = o.z - sub; r.w = o.w - sub;
        reinterpret_cast<float4*>(out)[(size_t)node * 10 + p] = r;
    }
}

// ---------------------------------------------------------------------------
extern "C" void kernel_launch(void* const* d_in, const int* in_sizes, int n_in,
                              void* d_out, int out_size) {
    const float*        x    = (const float*)d_in[0];
    const unsigned int* mask = (const unsigned int*)d_in[1];
    const int*          eidx = (const int*)d_in[2];
    const float*        W1   = (const float*)d_in[3];
    const float*        b1   = (const float*)d_in[4];
    const float*        W2   = (const float*)d_in[5];
    const float*        b2   = (const float*)d_in[6];
    float* out = (float*)d_out;

    const int N = in_sizes[0] / DF;   // 100000
    const int E = in_sizes[2] / 2;    // 1600000
    const int* row = eidx;
    const int* col = eidx + E;

    zero_kernel<<<(NN + 255) / 256, 256>>>();
    prep_kernel<<<(N * 32 + 255) / 256, 256>>>(x, mask, N);
    hist_kernel<<<(E + 255) / 256, 256>>>(row, E);
    scanA_kernel<<<SCAN_NB, 256>>>();
    scanB_kernel<<<1, 128>>>();
    scanC_kernel<<<SCAN_NB, 256>>>();
    edges_kernel<<<(E + 255) / 256, 256>>>(row, col, E);
    agg1_kernel<<<(N + 7) / 8, 256>>>(N);

    {
        int smem = (128 * 128 + 128 * 8) * (int)sizeof(float);
        cudaFuncSetAttribute(gemm1_kernel,
                             cudaFuncAttributeMaxDynamicSharedMemorySize, smem);
        gemm1_kernel<<<(N + 63) / 64, 128, smem>>>(W1, b1, N);
    }

    gemm2_kernel<<<(N + 63) / 64, 640>>>(W2, N);
    gather2_lsm_kernel<<<(N + 31) / 32, 320>>>(b2, out, N);
}

// round 7
// speedup vs baseline: 2.1669x; 1.0111x over previous
#include <cuda_runtime.h>
#include <cuda_fp16.h>
#include <math.h>

// PaGNN: N=100000 nodes, E=1600000 edges, D=128, H=128, C=40
#define NN 100000
#define DF 128
#define NC 40

#define SCAN_CHUNK 1024
#define SCAN_NB ((NN + SCAN_CHUNK - 1) / SCAN_CHUNK)   // 98

typedef unsigned long long ull;

// ---- scratch (device globals; no runtime allocation allowed) ---------------
__device__ __half g_xmh [NN * DF];     // x * mask in fp16 (gathered array)
__device__ uint4  g_mbits[NN];         // 128-bit mask per node (ballot layout)
__device__ float  g_hin  [NN * DF];    // normalized aggregation (conv1 input)
__device__ float  g_h1   [NN * DF];    // relu(conv1)
__device__ float  g_xw   [NN * NC];    // (h1 @ W2) * dinv[node]
__device__ int    g_rowcnt[NN];
__device__ int    g_rowptr[NN + 1];
__device__ int    g_wpos [NN];
__device__ int    g_scol [2000000];
__device__ float  g_dinv [NN];
__device__ int    g_bsum [SCAN_NB];

// ---- f32x2 helpers ----------------------------------------------------------
__device__ __forceinline__ ull pack2(float v) {
    ull r;
    unsigned u = __float_as_uint(v);
    asm("mov.b64 %0, {%1, %2};" : "=l"(r) : "r"(u), "r"(u));
    return r;
}
__device__ __forceinline__ void ffma2(ull& acc, ull a, ull b) {
    asm("fma.rn.f32x2 %0, %1, %2, %0;" : "+l"(acc) : "l"(a), "l"(b));
}
__device__ __forceinline__ void unpack2(ull v, float& lo, float& hi) {
    unsigned a, b;
    asm("mov.b64 {%0, %1}, %2;" : "=r"(a), "=r"(b) : "l"(v));
    lo = __uint_as_float(a);
    hi = __uint_as_float(b);
}

// ---------------------------------------------------------------------------
// 0) zero the histogram
// ---------------------------------------------------------------------------
__global__ void zero_kernel() {
    int i = blockIdx.x * blockDim.x + threadIdx.x;
    if (i < NN) g_rowcnt[i] = 0;
}

// ---------------------------------------------------------------------------
// 1) prep: xmh = fp16(x*mask) + 128-bit mask bitmap; one warp per node
// ---------------------------------------------------------------------------
__global__ void prep_kernel(const float* __restrict__ x,
                            const unsigned int* __restrict__ mask,
                            int n) {
    int node = (blockIdx.x * blockDim.x + threadIdx.x) >> 5;
    int lane = threadIdx.x & 31;
    if (node >= n) return;

    float4 xv = reinterpret_cast<const float4*>(x)[(size_t)node * 32 + lane];
    uint4  mv = reinterpret_cast<const uint4*>(mask)[(size_t)node * 32 + lane];

    float4 xm;
    xm.x = mv.x ? xv.x : 0.0f;
    xm.y = mv.y ? xv.y : 0.0f;
    xm.z = mv.z ? xv.z : 0.0f;
    xm.w = mv.w ? xv.w : 0.0f;

    __half2 h0 = __floats2half2_rn(xm.x, xm.y);
    __half2 h1 = __floats2half2_rn(xm.z, xm.w);
    uint2 packed;
    packed.x = *reinterpret_cast<unsigned*>(&h0);
    packed.y = *reinterpret_cast<unsigned*>(&h1);
    reinterpret_cast<uint2*>(g_xmh)[(size_t)node * 32 + lane] = packed;

    unsigned b0 = __ballot_sync(0xffffffffu, mv.x != 0u);
    unsigned b1 = __ballot_sync(0xffffffffu, mv.y != 0u);
    unsigned b2 = __ballot_sync(0xffffffffu, mv.z != 0u);
    unsigned b3 = __ballot_sync(0xffffffffu, mv.w != 0u);
    if (lane == 0) g_mbits[node] = make_uint4(b0, b1, b2, b3);
}

// ---------------------------------------------------------------------------
// 2) histogram of destination rows
// ---------------------------------------------------------------------------
__global__ void hist_kernel(const int* __restrict__ row, int E) {
    int e = blockIdx.x * blockDim.x + threadIdx.x;
    if (e < E) atomicAdd(&g_rowcnt[row[e]], 1);
}

// ---------------------------------------------------------------------------
// 3a) scan phase A: per-block sums (256 thr x 4 elems = 1024 per block)
// ---------------------------------------------------------------------------
__global__ void scanA_kernel() {
    __shared__ int swarp[8];
    int tid = threadIdx.x;
    int base = blockIdx.x * SCAN_CHUNK + tid * 4;

    int s = 0;
    #pragma unroll
    for (int k = 0; k < 4; k++) {
        int i = base + k;
        if (i < NN) s += g_rowcnt[i];
    }
    #pragma unroll
    for (int o = 16; o > 0; o >>= 1)
        s += __shfl_xor_sync(0xffffffffu, s, o);
    if ((tid & 31) == 0) swarp[tid >> 5] = s;
    __syncthreads();
    if (tid < 8) {
        int v = swarp[tid];
        #pragma unroll
        for (int o = 4; o > 0; o >>= 1)
            v += __shfl_xor_sync(0xffu, v, o);
        if (tid == 0) g_bsum[blockIdx.x] = v;
    }
}

// ---------------------------------------------------------------------------
// 3b) scan phase C: each block computes its own global offset from g_bsum
//     (98 elements, trivial), then intra-block scan; emits rowptr/wpos/dinv.
//     rowptr[NN] = E is written directly (total degree is known).
// ---------------------------------------------------------------------------
__global__ void scanC_kernel(int E) {
    __shared__ int sb[SCAN_NB];
    __shared__ int sh[256];
    int tid = threadIdx.x;
    if (tid < SCAN_NB) sb[tid] = g_bsum[tid];
    __syncthreads();

    int boff = 0;
    for (int i = 0; i < SCAN_NB; i++)
        boff += (i < blockIdx.x) ? sb[i] : 0;

    int base = blockIdx.x * SCAN_CHUNK + tid * 4;
    int c[4];
    int s = 0;
    #pragma unroll
    for (int k = 0; k < 4; k++) {
        int i = base + k;
        c[k] = (i < NN) ? g_rowcnt[i] : 0;
        s += c[k];
    }
    sh[tid] = s;
    __syncthreads();
    for (int off = 1; off < 256; off <<= 1) {
        int u = (tid >= off) ? sh[tid - off] : 0;
        __syncthreads();
        sh[tid] += u;
        __syncthreads();
    }

    int prefix = boff + sh[tid] - s;
    #pragma unroll
    for (int k = 0; k < 4; k++) {
        int i = base + k;
        if (i < NN) {
            g_rowptr[i] = prefix;
            g_wpos[i]   = prefix;
            g_dinv[i]   = rsqrtf((float)c[k] + 1.0f);
            prefix += c[k];
        }
    }
    if (blockIdx.x == 0 && tid == 0) g_rowptr[NN] = E;
}

// ---------------------------------------------------------------------------
// 4) bucket-fill CSR columns
// ---------------------------------------------------------------------------
__global__ void edges_kernel(const int* __restrict__ row,
                             const int* __restrict__ col, int E) {
    int e = blockIdx.x * blockDim.x + threadIdx.x;
    if (e >= E) return;
    int p = atomicAdd(&g_wpos[row[e]], 1);
    g_scol[p] = col[e];
}

// ---------------------------------------------------------------------------
// 5) pass-1 aggregation (gather, fp16 source): one warp per node, 4 feats/lane
// ---------------------------------------------------------------------------
__global__ void agg1_kernel(int n) {
    int node = (blockIdx.x * blockDim.x + threadIdx.x) >> 5;
    int lane = threadIdx.x & 31;
    if (node >= n) return;

    int s = g_rowptr[node];
    int e = g_rowptr[node + 1];

    float ax = 0.f, ay = 0.f, az = 0.f, aw = 0.f;
    int   cx = 0,   cy = 0,   cz = 0,   cw = 0;

    const uint2* xm2 = reinterpret_cast<const uint2*>(g_xmh);

    int j = s;
    for (; j + 4 <= e; j += 4) {
        int c0 = g_scol[j + 0];
        int c1 = g_scol[j + 1];
        int c2 = g_scol[j + 2];
        int c3 = g_scol[j + 3];
        uint2 r0 = xm2[(size_t)c0 * 32 + lane];
        uint2 r1 = xm2[(size_t)c1 * 32 + lane];
        uint2 r2 = xm2[(size_t)c2 * 32 + lane];
        uint2 r3 = xm2[(size_t)c3 * 32 + lane];
        uint4 b0 = g_mbits[c0];
        uint4 b1 = g_mbits[c1];
        uint4 b2 = g_mbits[c2];
        uint4 b3 = g_mbits[c3];

        float2 f;
        f = __half22float2(*reinterpret_cast<__half2*>(&r0.x)); ax += f.x; ay += f.y;
        f = __half22float2(*reinterpret_cast<__half2*>(&r0.y)); az += f.x; aw += f.y;
        f = __half22float2(*reinterpret_cast<__half2*>(&r1.x)); ax += f.x; ay += f.y;
        f = __half22float2(*reinterpret_cast<__half2*>(&r1.y)); az += f.x; aw += f.y;
        f = __half22float2(*reinterpret_cast<__half2*>(&r2.x)); ax += f.x; ay += f.y;
        f = __half22float2(*reinterpret_cast<__half2*>(&r2.y)); az += f.x; aw += f.y;
        f = __half22float2(*reinterpret_cast<__half2*>(&r3.x)); ax += f.x; ay += f.y;
        f = __half22float2(*reinterpret_cast<__half2*>(&r3.y)); az += f.x; aw += f.y;

        cx += ((b0.x >> lane) & 1u) + ((b1.x >> lane) & 1u) +
              ((b2.x >> lane) & 1u) + ((b3.x >> lane) & 1u);
        cy += ((b0.y >> lane) & 1u) + ((b1.y >> lane) & 1u) +
              ((b2.y >> lane) & 1u) + ((b3.y >> lane) & 1u);
        cz += ((b0.z >> lane) & 1u) + ((b1.z >> lane) & 1u) +
              ((b2.z >> lane) & 1u) + ((b3.z >> lane) & 1u);
        cw += ((b0.w >> lane) & 1u) + ((b1.w >> lane) & 1u) +
              ((b2.w >> lane) & 1u) + ((b3.w >> lane) & 1u);
    }
    for (; j < e; j++) {
        int c = g_scol[j];
        uint2 r  = xm2[(size_t)c * 32 + lane];
        uint4 bw = g_mbits[c];
        float2 f;
        f = __half22float2(*reinterpret_cast<__half2*>(&r.x)); ax += f.x; ay += f.y;
        f = __half22float2(*reinterpret_cast<__half2*>(&r.y)); az += f.x; aw += f.y;
        cx += (bw.x >> lane) & 1u;
        cy += (bw.y >> lane) & 1u;
        cz += (bw.z >> lane) & 1u;
        cw += (bw.w >> lane) & 1u;
    }

    float4 h;
    h.x = ax / fmaxf((float)cx, 1.0f);
    h.y = ay / fmaxf((float)cy, 1.0f);
    h.z = az / fmaxf((float)cz, 1.0f);
    h.w = aw / fmaxf((float)cw, 1.0f);
    reinterpret_cast<float4*>(g_hin)[(size_t)node * 32 + lane] = h;
}

// ---------------------------------------------------------------------------
// 6) h1 = relu(hin @ W1 + b1): 8-node register tile, packed f32x2 FMA.
//    128 threads (tid = output col), 64 nodes/block.
// ---------------------------------------------------------------------------
__global__ void gemm1_kernel(const float* __restrict__ W1,
                             const float* __restrict__ b1, int n) {
    extern __shared__ float sh[];
    float* shW  = sh;               // [128][128]  64KB
    float* shHT = sh + 128 * 128;   // [128][8]    4KB
    int tid = threadIdx.x;

    for (int i = tid; i < 128 * 128; i += 128) shW[i] = W1[i];
    ull bb = pack2(b1[tid]);
    int base = blockIdx.x * 64;
    __syncthreads();

    for (int g = 0; g < 8; g++) {
        int nb = base + g * 8;
        {
            float t[8];
            #pragma unroll
            for (int nn = 0; nn < 8; nn++) {
                int node = nb + nn;
                t[nn] = (node < n) ? g_hin[(size_t)node * 128 + tid] : 0.0f;
            }
            reinterpret_cast<float4*>(shHT + tid * 8)[0] =
                make_float4(t[0], t[1], t[2], t[3]);
            reinterpret_cast<float4*>(shHT + tid * 8)[1] =
                make_float4(t[4], t[5], t[6], t[7]);
        }
        __syncthreads();

        ull a01 = bb, a23 = bb, a45 = bb, a67 = bb;
        #pragma unroll
        for (int k = 0; k < 128; k++) {
            ulonglong2 p0 = reinterpret_cast<const ulonglong2*>(shHT + k * 8)[0];
            ulonglong2 p1 = reinterpret_cast<const ulonglong2*>(shHT + k * 8)[1];
            ull ww = pack2(shW[k * 128 + tid]);
            ffma2(a01, p0.x, ww);
            ffma2(a23, p0.y, ww);
            ffma2(a45, p1.x, ww);
            ffma2(a67, p1.y, ww);
        }

        float v[8];
        unpack2(a01, v[0], v[1]);
        unpack2(a23, v[2], v[3]);
        unpack2(a45, v[4], v[5]);
        unpack2(a67, v[6], v[7]);
        #pragma unroll
        for (int nn = 0; nn < 8; nn++) {
            int node = nb + nn;
            if (node < n)
                g_h1[(size_t)node * 128 + tid] = fmaxf(v[nn], 0.0f);
        }
        __syncthreads();
    }
}

// ---------------------------------------------------------------------------
// 7) xw = (h1 @ W2) * dinv[node]: 640 threads, 64 nodes/block
// ---------------------------------------------------------------------------
#define HP 132
__global__ void gemm2_kernel(const float* __restrict__ W2, int n) {
    __shared__ float shW[128 * 40];
    __shared__ float shH[64 * HP];
    int tid = threadIdx.x;

    for (int i = tid; i < 128 * 40; i += 640) shW[i] = W2[i];

    int base = blockIdx.x * 64;
    for (int i = tid; i < 64 * 128; i += 640) {
        int s  = i >> 7;
        int kk = i & 127;
        int node = base + s;
        shH[s * HP + kk] = (node < n) ? g_h1[(size_t)node * 128 + kk] : 0.0f;
    }
    __syncthreads();

    int s  = tid / 10;
    int j4 = tid - s * 10;
    int node = base + s;
    if (node >= n) return;

    ull a01 = 0, a23 = 0;
    #pragma unroll
    for (int k = 0; k < 128; k++) {
        ull hh = pack2(shH[s * HP + k]);
        ulonglong2 w =
            *reinterpret_cast<const ulonglong2*>(shW + k * 40 + j4 * 4);
        ffma2(a01, hh, w.x);
        ffma2(a23, hh, w.y);
    }

    float dc = g_dinv[node];
    float4 o;
    unpack2(a01, o.x, o.y);
    unpack2(a23, o.z, o.w);
    o.x *= dc; o.y *= dc; o.z *= dc; o.w *= dc;
    reinterpret_cast<float4*>(g_xw)[(size_t)node * 10 + j4] = o;
}

// ---------------------------------------------------------------------------
// 8) fused GCN gather + self-loop + bias + log_softmax.
// ---------------------------------------------------------------------------
__global__ void gather2_lsm_kernel(const float* __restrict__ b2,
                                   float* __restrict__ out, int n) {
    __shared__ float shB[40];
    __shared__ float shV[320];
    __shared__ float shM[32];
    __shared__ float shL[32];
    int tid = threadIdx.x;
    if (tid < 40) shB[tid] = b2[tid];
    __syncthreads();

    int s = tid / 10;
    int p = tid - s * 10;
    int node = blockIdx.x * 32 + s;
    bool live = (node < n);

    const float4* xw4 = reinterpret_cast<const float4*>(g_xw);

    float4 o = make_float4(0.f, 0.f, 0.f, 0.f);
    if (live) {
        float dr = g_dinv[node];
        int a = g_rowptr[node];
        int b = g_rowptr[node + 1];

        float4 acc = xw4[(size_t)node * 10 + p];
        int j = a;
        for (; j + 4 <= b; j += 4) {
            int c0 = g_scol[j + 0];
            int c1 = g_scol[j + 1];
            int c2 = g_scol[j + 2];
            int c3 = g_scol[j + 3];
            float4 v0 = xw4[(size_t)c0 * 10 + p];
            float4 v1 = xw4[(size_t)c1 * 10 + p];
            float4 v2 = xw4[(size_t)c2 * 10 + p];
            float4 v3 = xw4[(size_t)c3 * 10 + p];
            acc.x += (v0.x + v1.x) + (v2.x + v3.x);
            acc.y += (v0.y + v1.y) + (v2.y + v3.y);
            acc.z += (v0.z + v1.z) + (v2.z + v3.z);
            acc.w += (v0.w + v1.w) + (v2.w + v3.w);
        }
        for (; j < b; j++) {
            int c = g_scol[j];
            float4 v = xw4[(size_t)c * 10 + p];
            acc.x += v.x; acc.y += v.y; acc.z += v.z; acc.w += v.w;
        }
        o.x = fmaf(acc.x, dr, shB[p * 4 + 0]);
        o.y = fmaf(acc.y, dr, shB[p * 4 + 1]);
        o.z = fmaf(acc.z, dr, shB[p * 4 + 2]);
        o.w = fmaf(acc.w, dr, shB[p * 4 + 3]);
    }

    shV[tid] = live ? fmaxf(fmaxf(o.x, o.y), fmaxf(o.z, o.w)) : -INFINITY;
    __syncthreads();
    if (tid < 32) {
        float m = shV[tid * 10];
        #pragma unroll
        for (int i = 1; i < 10; i++) m = fmaxf(m, shV[tid * 10 + i]);
        shM[tid] = m;
    }
    __syncthreads();

    float m = shM[s];
    float le = live ? (expf(o.x - m) + expf(o.y - m) +
                       expf(o.z - m) + expf(o.w - m)) : 0.0f;
    shV[tid] = le;
    __syncthreads();
    if (tid < 32) {
        float su = shV[tid * 10];
        #pragma unroll
        for (int i = 1; i < 10; i++) su += shV[tid * 10 + i];
        shL[tid] = logf(su);
    }
    __syncthreads();

    if (live) {
        float sub = m + shL[s];
        float4 r;
        r.x = o.x - sub; r.y = o.y - sub; r.z = o.z - sub; r.w = o.w - sub;
        reinterpret_cast<float4*>(out)[(size_t)node * 10 + p] = r;
    }
}

// ---------------------------------------------------------------------------
extern "C" void kernel_launch(void* const* d_in, const int* in_sizes, int n_in,
                              void* d_out, int out_size) {
    const float*        x    = (const float*)d_in[0];
    const unsigned int* mask = (const unsigned int*)d_in[1];
    const int*          eidx = (const int*)d_in[2];
    const float*        W1   = (const float*)d_in[3];
    const float*        b1   = (const float*)d_in[4];
    const float*        W2   = (const float*)d_in[5];
    const float*        b2   = (const float*)d_in[6];
    float* out = (float*)d_out;

    const int N = in_sizes[0] / DF;   // 100000
    const int E = in_sizes[2] / 2;    // 1600000
    const int* row = eidx;
    const int* col = eidx + E;

    zero_kernel<<<(NN + 255) / 256, 256>>>();
    prep_kernel<<<(N * 32 + 255) / 256, 256>>>(x, mask, N);
    hist_kernel<<<(E + 255) / 256, 256>>>(row, E);
    scanA_kernel<<<SCAN_NB, 256>>>();
    scanC_kernel<<<SCAN_NB, 256>>>(E);
    edges_kernel<<<(E + 255) / 256, 256>>>(row, col, E);
    agg1_kernel<<<(N + 7) / 8, 256>>>(N);

    {
        int smem = (128 * 128 + 128 * 8) * (int)sizeof(float);
        cudaFuncSetAttribute(gemm1_kernel,
                             cudaFuncAttributeMaxDynamicSharedMemorySize, smem);
        gemm1_kernel<<<(N + 63) / 64, 128, smem>>>(W1, b1, N);
    }

    gemm2_kernel<<<(N + 63) / 64, 640>>>(W2, N);
    gather2_lsm_kernel<<<(N + 31) / 32, 320>>>(b2, out, N);
}

// round 8
// speedup vs baseline: 2.2004x; 1.0155x over previous
#include <cuda_runtime.h>
#include <cuda_fp16.h>
#include <math.h>

// PaGNN: N=100000 nodes, E=1600000 edges, D=128, H=128, C=40
#define NN 100000
#define DF 128
#define NC 40

#define SCAN_CHUNK 1024
#define SCAN_NB ((NN + SCAN_CHUNK - 1) / SCAN_CHUNK)   // 98

typedef unsigned long long ull;

// ---- scratch (device globals; no runtime allocation allowed) ---------------
__device__ __half g_xmh [NN * DF];     // x * mask in fp16 (gathered array)
__device__ uint4  g_mbits[NN];         // 128-bit mask per node (ballot layout)
__device__ float  g_hin  [NN * DF];    // normalized aggregation (conv1 input)
__device__ float  g_h1   [NN * DF];    // relu(conv1)
__device__ float  g_xw   [NN * NC];    // (h1 @ W2) * dinv[node]
__device__ int    g_rowcnt[NN];
__device__ int    g_rowptr[NN + 1];
__device__ int    g_wpos [NN];
__device__ int    g_scol [2000000];
__device__ float  g_dinv [NN];
__device__ int    g_bsum [SCAN_NB];

// ---- f32x2 helpers ----------------------------------------------------------
__device__ __forceinline__ ull pack2(float v) {
    ull r;
    unsigned u = __float_as_uint(v);
    asm("mov.b64 %0, {%1, %2};" : "=l"(r) : "r"(u), "r"(u));
    return r;
}
__device__ __forceinline__ void ffma2(ull& acc, ull a, ull b) {
    asm("fma.rn.f32x2 %0, %1, %2, %0;" : "+l"(acc) : "l"(a), "l"(b));
}
__device__ __forceinline__ void unpack2(ull v, float& lo, float& hi) {
    unsigned a, b;
    asm("mov.b64 {%0, %1}, %2;" : "=r"(a), "=r"(b) : "l"(v));
    lo = __uint_as_float(a);
    hi = __uint_as_float(b);
}

// ---------------------------------------------------------------------------
// 1) prep: xmh = fp16(x*mask) + mask bitmap; also zeroes rowcnt (hist runs
//    strictly after prep in stream order). One warp per node.
// ---------------------------------------------------------------------------
__global__ void prep_kernel(const float* __restrict__ x,
                            const unsigned int* __restrict__ mask,
                            int n) {
    int node = (blockIdx.x * blockDim.x + threadIdx.x) >> 5;
    int lane = threadIdx.x & 31;
    if (node >= n) return;

    float4 xv = reinterpret_cast<const float4*>(x)[(size_t)node * 32 + lane];
    uint4  mv = reinterpret_cast<const uint4*>(mask)[(size_t)node * 32 + lane];

    float4 xm;
    xm.x = mv.x ? xv.x : 0.0f;
    xm.y = mv.y ? xv.y : 0.0f;
    xm.z = mv.z ? xv.z : 0.0f;
    xm.w = mv.w ? xv.w : 0.0f;

    __half2 h0 = __floats2half2_rn(xm.x, xm.y);
    __half2 h1 = __floats2half2_rn(xm.z, xm.w);
    uint2 packed;
    packed.x = *reinterpret_cast<unsigned*>(&h0);
    packed.y = *reinterpret_cast<unsigned*>(&h1);
    reinterpret_cast<uint2*>(g_xmh)[(size_t)node * 32 + lane] = packed;

    unsigned b0 = __ballot_sync(0xffffffffu, mv.x != 0u);
    unsigned b1 = __ballot_sync(0xffffffffu, mv.y != 0u);
    unsigned b2 = __ballot_sync(0xffffffffu, mv.z != 0u);
    unsigned b3 = __ballot_sync(0xffffffffu, mv.w != 0u);
    if (lane == 0) {
        g_mbits[node] = make_uint4(b0, b1, b2, b3);
        g_rowcnt[node] = 0;
    }
}

// ---------------------------------------------------------------------------
// 2) histogram of destination rows
// ---------------------------------------------------------------------------
__global__ void hist_kernel(const int* __restrict__ row, int E) {
    int e = blockIdx.x * blockDim.x + threadIdx.x;
    if (e < E) atomicAdd(&g_rowcnt[row[e]], 1);
}

// ---------------------------------------------------------------------------
// 3a) scan phase A: per-block sums
// ---------------------------------------------------------------------------
__global__ void scanA_kernel() {
    __shared__ int swarp[8];
    int tid = threadIdx.x;
    int base = blockIdx.x * SCAN_CHUNK + tid * 4;

    int s = 0;
    #pragma unroll
    for (int k = 0; k < 4; k++) {
        int i = base + k;
        if (i < NN) s += g_rowcnt[i];
    }
    #pragma unroll
    for (int o = 16; o > 0; o >>= 1)
        s += __shfl_xor_sync(0xffffffffu, s, o);
    if ((tid & 31) == 0) swarp[tid >> 5] = s;
    __syncthreads();
    if (tid < 8) {
        int v = swarp[tid];
        #pragma unroll
        for (int o = 4; o > 0; o >>= 1)
            v += __shfl_xor_sync(0xffu, v, o);
        if (tid == 0) g_bsum[blockIdx.x] = v;
    }
}

// ---------------------------------------------------------------------------
// 3b) scan phase C: block offset from g_bsum + intra-block scan
// ---------------------------------------------------------------------------
__global__ void scanC_kernel(int E) {
    __shared__ int sb[SCAN_NB];
    __shared__ int sh[256];
    int tid = threadIdx.x;
    if (tid < SCAN_NB) sb[tid] = g_bsum[tid];
    __syncthreads();

    int boff = 0;
    for (int i = 0; i < SCAN_NB; i++)
        boff += (i < blockIdx.x) ? sb[i] : 0;

    int base = blockIdx.x * SCAN_CHUNK + tid * 4;
    int c[4];
    int s = 0;
    #pragma unroll
    for (int k = 0; k < 4; k++) {
        int i = base + k;
        c[k] = (i < NN) ? g_rowcnt[i] : 0;
        s += c[k];
    }
    sh[tid] = s;
    __syncthreads();
    for (int off = 1; off < 256; off <<= 1) {
        int u = (tid >= off) ? sh[tid - off] : 0;
        __syncthreads();
        sh[tid] += u;
        __syncthreads();
    }

    int prefix = boff + sh[tid] - s;
    #pragma unroll
    for (int k = 0; k < 4; k++) {
        int i = base + k;
        if (i < NN) {
            g_rowptr[i] = prefix;
            g_wpos[i]   = prefix;
            g_dinv[i]   = rsqrtf((float)c[k] + 1.0f);
            prefix += c[k];
        }
    }
    if (blockIdx.x == 0 && tid == 0) g_rowptr[NN] = E;
}

// ---------------------------------------------------------------------------
// 4) bucket-fill CSR columns
// ---------------------------------------------------------------------------
__global__ void edges_kernel(const int* __restrict__ row,
                             const int* __restrict__ col, int E) {
    int e = blockIdx.x * blockDim.x + threadIdx.x;
    if (e >= E) return;
    int p = atomicAdd(&g_wpos[row[e]], 1);
    g_scol[p] = col[e];
}

// ---------------------------------------------------------------------------
// 5) pass-1 aggregation (gather, fp16 source): one warp per node
// ---------------------------------------------------------------------------
__global__ void agg1_kernel(int n) {
    int node = (blockIdx.x * blockDim.x + threadIdx.x) >> 5;
    int lane = threadIdx.x & 31;
    if (node >= n) return;

    int s = g_rowptr[node];
    int e = g_rowptr[node + 1];

    float ax = 0.f, ay = 0.f, az = 0.f, aw = 0.f;
    int   cx = 0,   cy = 0,   cz = 0,   cw = 0;

    const uint2* xm2 = reinterpret_cast<const uint2*>(g_xmh);

    int j = s;
    for (; j + 4 <= e; j += 4) {
        int c0 = g_scol[j + 0];
        int c1 = g_scol[j + 1];
        int c2 = g_scol[j + 2];
        int c3 = g_scol[j + 3];
        uint2 r0 = xm2[(size_t)c0 * 32 + lane];
        uint2 r1 = xm2[(size_t)c1 * 32 + lane];
        uint2 r2 = xm2[(size_t)c2 * 32 + lane];
        uint2 r3 = xm2[(size_t)c3 * 32 + lane];
        uint4 b0 = g_mbits[c0];
        uint4 b1 = g_mbits[c1];
        uint4 b2 = g_mbits[c2];
        uint4 b3 = g_mbits[c3];

        float2 f;
        f = __half22float2(*reinterpret_cast<__half2*>(&r0.x)); ax += f.x; ay += f.y;
        f = __half22float2(*reinterpret_cast<__half2*>(&r0.y)); az += f.x; aw += f.y;
        f = __half22float2(*reinterpret_cast<__half2*>(&r1.x)); ax += f.x; ay += f.y;
        f = __half22float2(*reinterpret_cast<__half2*>(&r1.y)); az += f.x; aw += f.y;
        f = __half22float2(*reinterpret_cast<__half2*>(&r2.x)); ax += f.x; ay += f.y;
        f = __half22float2(*reinterpret_cast<__half2*>(&r2.y)); az += f.x; aw += f.y;
        f = __half22float2(*reinterpret_cast<__half2*>(&r3.x)); ax += f.x; ay += f.y;
        f = __half22float2(*reinterpret_cast<__half2*>(&r3.y)); az += f.x; aw += f.y;

        cx += ((b0.x >> lane) & 1u) + ((b1.x >> lane) & 1u) +
              ((b2.x >> lane) & 1u) + ((b3.x >> lane) & 1u);
        cy += ((b0.y >> lane) & 1u) + ((b1.y >> lane) & 1u) +
              ((b2.y >> lane) & 1u) + ((b3.y >> lane) & 1u);
        cz += ((b0.z >> lane) & 1u) + ((b1.z >> lane) & 1u) +
              ((b2.z >> lane) & 1u) + ((b3.z >> lane) & 1u);
        cw += ((b0.w >> lane) & 1u) + ((b1.w >> lane) & 1u) +
              ((b2.w >> lane) & 1u) + ((b3.w >> lane) & 1u);
    }
    for (; j < e; j++) {
        int c = g_scol[j];
        uint2 r  = xm2[(size_t)c * 32 + lane];
        uint4 bw = g_mbits[c];
        float2 f;
        f = __half22float2(*reinterpret_cast<__half2*>(&r.x)); ax += f.x; ay += f.y;
        f = __half22float2(*reinterpret_cast<__half2*>(&r.y)); az += f.x; aw += f.y;
        cx += (bw.x >> lane) & 1u;
        cy += (bw.y >> lane) & 1u;
        cz += (bw.z >> lane) & 1u;
        cw += (bw.w >> lane) & 1u;
    }

    float4 h;
    h.x = ax / fmaxf((float)cx, 1.0f);
    h.y = ay / fmaxf((float)cy, 1.0f);
    h.z = az / fmaxf((float)cz, 1.0f);
    h.w = aw / fmaxf((float)cw, 1.0f);
    reinterpret_cast<float4*>(g_hin)[(size_t)node * 32 + lane] = h;
}

// ---------------------------------------------------------------------------
// 6) h1 = relu(hin @ W1 + b1): 256 threads/block, 32 nodes/block.
//    thread = (col j = tid&127, node-half nh = tid>>7); each thread owns
//    4 nodes (2 f32x2 accumulators). 68KB smem -> 3 blocks/SM = 24 warps/SM
//    (2x the previous warp count, to hide LDS latency).
// ---------------------------------------------------------------------------
__global__ void gemm1_kernel(const float* __restrict__ W1,
                             const float* __restrict__ b1, int n) {
    extern __shared__ float sh[];
    float* shW  = sh;               // [128][128]  64KB
    float* shHT = sh + 128 * 128;   // [128][8]    4KB (transposed 8-node tile)
    int tid = threadIdx.x;
    int j   = tid & 127;            // output column
    int nh  = tid >> 7;             // node half (0: nodes 0-3, 1: nodes 4-7)

    for (int i = tid; i < 128 * 128; i += 256) shW[i] = W1[i];
    ull bb = pack2(b1[j]);
    int base = blockIdx.x * 32;
    __syncthreads();

    for (int g = 0; g < 4; g++) {
        int nb = base + g * 8;
        // stage transposed 8-node tile: thread (j, nh) loads nodes nh*4..nh*4+3
        // at feature row j  (coalesced across j for each node)
        {
            float t[4];
            #pragma unroll
            for (int nn = 0; nn < 4; nn++) {
                int node = nb + nh * 4 + nn;
                t[nn] = (node < n) ? g_hin[(size_t)node * 128 + j] : 0.0f;
            }
            reinterpret_cast<float4*>(shHT + j * 8 + nh * 4)[0] =
                make_float4(t[0], t[1], t[2], t[3]);
        }
        __syncthreads();

        ull a01 = bb, a23 = bb;
        #pragma unroll
        for (int k = 0; k < 128; k++) {
            ulonglong2 p =
                reinterpret_cast<const ulonglong2*>(shHT + k * 8 + nh * 4)[0];
            ull ww = pack2(shW[k * 128 + j]);
            ffma2(a01, p.x, ww);
            ffma2(a23, p.y, ww);
        }

        float v[4];
        unpack2(a01, v[0], v[1]);
        unpack2(a23, v[2], v[3]);
        #pragma unroll
        for (int nn = 0; nn < 4; nn++) {
            int node = nb + nh * 4 + nn;
            if (node < n)
                g_h1[(size_t)node * 128 + j] = fmaxf(v[nn], 0.0f);
        }
        __syncthreads();
    }
}

// ---------------------------------------------------------------------------
// 7) xw = (h1 @ W2) * dinv[node]: 640 threads, 64 nodes/block
// ---------------------------------------------------------------------------
#define HP 132
__global__ void gemm2_kernel(const float* __restrict__ W2, int n) {
    __shared__ float shW[128 * 40];
    __shared__ float shH[64 * HP];
    int tid = threadIdx.x;

    for (int i = tid; i < 128 * 40; i += 640) shW[i] = W2[i];

    int base = blockIdx.x * 64;
    for (int i = tid; i < 64 * 128; i += 640) {
        int s  = i >> 7;
        int kk = i & 127;
        int node = base + s;
        shH[s * HP + kk] = (node < n) ? g_h1[(size_t)node * 128 + kk] : 0.0f;
    }
    __syncthreads();

    int s  = tid / 10;
    int j4 = tid - s * 10;
    int node = base + s;
    if (node >= n) return;

    ull a01 = 0, a23 = 0;
    #pragma unroll
    for (int k = 0; k < 128; k++) {
        ull hh = pack2(shH[s * HP + k]);
        ulonglong2 w =
            *reinterpret_cast<const ulonglong2*>(shW + k * 40 + j4 * 4);
        ffma2(a01, hh, w.x);
        ffma2(a23, hh, w.y);
    }

    float dc = g_dinv[node];
    float4 o;
    unpack2(a01, o.x, o.y);
    unpack2(a23, o.z, o.w);
    o.x *= dc; o.y *= dc; o.z *= dc; o.w *= dc;
    reinterpret_cast<float4*>(g_xw)[(size_t)node * 10 + j4] = o;
}

// ---------------------------------------------------------------------------
// 8) fused GCN gather + self-loop + bias + log_softmax.
// ---------------------------------------------------------------------------
__global__ void gather2_lsm_kernel(const float* __restrict__ b2,
                                   float* __restrict__ out, int n) {
    __shared__ float shB[40];
    __shared__ float shV[320];
    __shared__ float shM[32];
    __shared__ float shL[32];
    int tid = threadIdx.x;
    if (tid < 40) shB[tid] = b2[tid];
    __syncthreads();

    int s = tid / 10;
    int p = tid - s * 10;
    int node = blockIdx.x * 32 + s;
    bool live = (node < n);

    const float4* xw4 = reinterpret_cast<const float4*>(g_xw);

    float4 o = make_float4(0.f, 0.f, 0.f, 0.f);
    if (live) {
        float dr = g_dinv[node];
        int a = g_rowptr[node];
        int b = g_rowptr[node + 1];

        float4 acc = xw4[(size_t)node * 10 + p];
        int j = a;
        for (; j + 4 <= b; j += 4) {
            int c0 = g_scol[j + 0];
            int c1 = g_scol[j + 1];
            int c2 = g_scol[j + 2];
            int c3 = g_scol[j + 3];
            float4 v0 = xw4[(size_t)c0 * 10 + p];
            float4 v1 = xw4[(size_t)c1 * 10 + p];
            float4 v2 = xw4[(size_t)c2 * 10 + p];
            float4 v3 = xw4[(size_t)c3 * 10 + p];
            acc.x += (v0.x + v1.x) + (v2.x + v3.x);
            acc.y += (v0.y + v1.y) + (v2.y + v3.y);
            acc.z += (v0.z + v1.z) + (v2.z + v3.z);
            acc.w += (v0.w + v1.w) + (v2.w + v3.w);
        }
        for (; j < b; j++) {
            int c = g_scol[j];
            float4 v = xw4[(size_t)c * 10 + p];
            acc.x += v.x; acc.y += v.y; acc.z += v.z; acc.w += v.w;
        }
        o.x = fmaf(acc.x, dr, shB[p * 4 + 0]);
        o.y = fmaf(acc.y, dr, shB[p * 4 + 1]);
        o.z = fmaf(acc.z, dr, shB[p * 4 + 2]);
        o.w = fmaf(acc.w, dr, shB[p * 4 + 3]);
    }

    shV[tid] = live ? fmaxf(fmaxf(o.x, o.y), fmaxf(o.z, o.w)) : -INFINITY;
    __syncthreads();
    if (tid < 32) {
        float m = shV[tid * 10];
        #pragma unroll
        for (int i = 1; i < 10; i++) m = fmaxf(m, shV[tid * 10 + i]);
        shM[tid] = m;
    }
    __syncthreads();

    float m = shM[s];
    float le = live ? (expf(o.x - m) + expf(o.y - m) +
                       expf(o.z - m) + expf(o.w - m)) : 0.0f;
    shV[tid] = le;
    __syncthreads();
    if (tid < 32) {
        float su = shV[tid * 10];
        #pragma unroll
        for (int i = 1; i < 10; i++) su += shV[tid * 10 + i];
        shL[tid] = logf(su);
    }
    __syncthreads();

    if (live) {
        float sub = m + shL[s];
        float4 r;
        r.x = o.x - sub; r.y = o.y - sub; r.z = o.z - sub; r.w = o.w - sub;
        reinterpret_cast<float4*>(out)[(size_t)node * 10 + p] = r;
    }
}

// ---------------------------------------------------------------------------
extern "C" void kernel_launch(void* const* d_in, const int* in_sizes, int n_in,
                              void* d_out, int out_size) {
    const float*        x    = (const float*)d_in[0];
    const unsigned int* mask = (const unsigned int*)d_in[1];
    const int*          eidx = (const int*)d_in[2];
    const float*        W1   = (const float*)d_in[3];
    const float*        b1   = (const float*)d_in[4];
    const float*        W2   = (const float*)d_in[5];
    const float*        b2   = (const float*)d_in[6];
    float* out = (float*)d_out;

    const int N = in_sizes[0] / DF;   // 100000
    const int E = in_sizes[2] / 2;    // 1600000
    const int* row = eidx;
    const int* col = eidx + E;

    prep_kernel<<<(N * 32 + 255) / 256, 256>>>(x, mask, N);
    hist_kernel<<<(E + 255) / 256, 256>>>(row, E);
    scanA_kernel<<<SCAN_NB, 256>>>();
    scanC_kernel<<<SCAN_NB, 256>>>(E);
    edges_kernel<<<(E + 255) / 256, 256>>>(row, col, E);
    agg1_kernel<<<(N + 7) / 8, 256>>>(N);

    {
        int smem = (128 * 128 + 128 * 8) * (int)sizeof(float);
        cudaFuncSetAttribute(gemm1_kernel,
                             cudaFuncAttributeMaxDynamicSharedMemorySize, smem);
        gemm1_kernel<<<(N + 31) / 32, 256, smem>>>(W1, b1, N);
    }

    gemm2_kernel<<<(N + 63) / 64, 640>>>(W2, N);
    gather2_lsm_kernel<<<(N + 31) / 32, 320>>>(b2, out, N);
}